// round 9
// baseline (speedup 1.0000x reference)
#include <cuda_runtime.h>
#include <math.h>

#define NB 16
#define NS 512
#define NH 16
#define ND 64
#define NHID 1024
#define NROW (NB*NS)        // 8192
#define NBH (NB*NH)         // 256
#define NTOK (NBH*NS*ND)    // 8388608

// ---------------- scratch (static __device__, allocation-guard safe) ----------------
__device__ __align__(16) float g_proj[2][NROW*NHID];
__device__ __align__(16) float g_c[2][NTOK];           // (B,H,S,D)
__device__ __align__(16) float g_q[2][NTOK];
__device__ __align__(16) float g_k[2][NTOK];
__device__ __align__(16) float g_v[2][NTOK];
__device__ __align__(16) float g_o[2][NTOK];
__device__ __align__(16) float g_comb[NBH*NS*2*ND];    // (B,H,S,128)

// ---------------- tf32 mma helpers ----------------
__device__ __forceinline__ unsigned cvt_tf32(float x) {
    unsigned u; asm("cvt.rna.tf32.f32 %0, %1;" : "=r"(u) : "f"(x)); return u;
}
__device__ __forceinline__ float tf32f(float x) {
    return __uint_as_float(cvt_tf32(x));
}
__device__ __forceinline__ void mma_tf32(float c[4], const unsigned a[4], unsigned b0, unsigned b1) {
    asm("mma.sync.aligned.m16n8k8.row.col.f32.tf32.tf32.f32 "
        "{%0,%1,%2,%3}, {%4,%5,%6,%7}, {%8,%9}, {%0,%1,%2,%3};"
        : "+f"(c[0]), "+f"(c[1]), "+f"(c[2]), "+f"(c[3])
        : "r"(a[0]), "r"(a[1]), "r"(a[2]), "r"(a[3]), "r"(b0), "r"(b1));
}

// ============ big projection GEMM (tf32 tensor cores) ============
// C[M,1024] = A[M,K] @ W[1024,K]^T + bias.  CTA tile 128x128, BK=32.
#define GPA 36    // 32 + 4 pad -> (4g+t) bank-unique fragment gathers
__global__ void gemm_tf32_kernel(const float* __restrict__ A,
                                 const float* __restrict__ W,
                                 const float* __restrict__ bias,
                                 int K, int which) {
    __shared__ __align__(16) float As[128*GPA];
    __shared__ __align__(16) float Ws[128*GPA];
    float* C = g_proj[which];
    int tid = threadIdx.x;
    int wid = tid >> 5, lane = tid & 31;
    int wm = wid >> 1, wn = wid & 1;
    int g = lane >> 2, t = lane & 3;
    int m0 = blockIdx.y * 128, n0 = blockIdx.x * 128;
    int lr = tid >> 3;           // 0..31
    int lc = (tid & 7) * 4;      // 0..28
    float acc[2][8][4] = {};
    for (int k0 = 0; k0 < K; k0 += 32) {
        #pragma unroll
        for (int i = 0; i < 4; i++) {
            int r = lr + i*32;
            float4 av = *(const float4*)(A + (size_t)(m0 + r)*K + k0 + lc);
            float4 wv = *(const float4*)(W + (size_t)(n0 + r)*K + k0 + lc);
            float* ad = As + r*GPA + lc;
            float* wd = Ws + r*GPA + lc;
            ad[0]=tf32f(av.x); ad[1]=tf32f(av.y); ad[2]=tf32f(av.z); ad[3]=tf32f(av.w);
            wd[0]=tf32f(wv.x); wd[1]=tf32f(wv.y); wd[2]=tf32f(wv.z); wd[3]=tf32f(wv.w);
        }
        __syncthreads();
        #pragma unroll
        for (int kc = 0; kc < 4; kc++) {
            unsigned a[2][4];
            #pragma unroll
            for (int mf = 0; mf < 2; mf++) {
                const float* ab = As + (wm*32 + mf*16 + g)*GPA + kc*8 + t;
                a[mf][0] = __float_as_uint(ab[0]);
                a[mf][1] = __float_as_uint(ab[8*GPA]);
                a[mf][2] = __float_as_uint(ab[4]);
                a[mf][3] = __float_as_uint(ab[8*GPA+4]);
            }
            #pragma unroll
            for (int nf = 0; nf < 8; nf++) {
                const float* bb = Ws + (wn*64 + nf*8 + g)*GPA + kc*8 + t;
                unsigned b0 = __float_as_uint(bb[0]);
                unsigned b1 = __float_as_uint(bb[4]);
                mma_tf32(acc[0][nf], a[0], b0, b1);
                mma_tf32(acc[1][nf], a[1], b0, b1);
            }
        }
        __syncthreads();
    }
    #pragma unroll
    for (int mf = 0; mf < 2; mf++) {
        int r0 = m0 + wm*32 + mf*16 + g;
        #pragma unroll
        for (int nf = 0; nf < 8; nf++) {
            int c = n0 + wn*64 + nf*8 + 2*t;
            float bx = bias[c], by = bias[c+1];
            *(float2*)(C + (size_t)r0*NHID + c) =
                make_float2(acc[mf][nf][0] + bx, acc[mf][nf][1] + by);
            *(float2*)(C + (size_t)(r0+8)*NHID + c) =
                make_float2(acc[mf][nf][2] + bx, acc[mf][nf][3] + by);
        }
    }
}

// ---------------- LN + l2-normalize + D^-0.5, writes (B,H,S,D) layout ----------------
__device__ __forceinline__ float breduce256(float v, float* red) {
    #pragma unroll
    for (int o = 16; o > 0; o >>= 1) v += __shfl_xor_sync(0xffffffffu, v, o);
    int tid = threadIdx.x;
    if ((tid & 31) == 0) red[tid >> 5] = v;
    __syncthreads();
    float t = 0.f;
    #pragma unroll
    for (int i = 0; i < 8; i++) t += red[i];
    __syncthreads();
    return t;
}

__global__ void ln_l2_kernel(const float* __restrict__ g, const float* __restrict__ b, int which) {
    __shared__ float red[8];
    int row = blockIdx.x;
    int tid = threadIdx.x;
    const float* y = g_proj[which] + (size_t)row * NHID;
    float v[4], sum = 0.f;
    #pragma unroll
    for (int i=0;i<4;i++){ v[i] = y[tid + i*256]; sum += v[i]; }
    sum = breduce256(sum, red);
    float mu = sum * (1.f/NHID);
    float sq = 0.f;
    #pragma unroll
    for (int i=0;i<4;i++){ float d = v[i]-mu; sq += d*d; }
    sq = breduce256(sq, red);
    float rstd = rsqrtf(sq*(1.f/NHID) + 1e-5f);
    float ln[4], s2 = 0.f;
    #pragma unroll
    for (int i=0;i<4;i++){ int n = tid+i*256; ln[i] = (v[i]-mu)*rstd*g[n] + b[n]; s2 += ln[i]*ln[i]; }
    s2 = breduce256(s2, red);
    float scale = 0.125f / fmaxf(sqrtf(s2), 1e-12f);
    int bb = row >> 9, s = row & 511;
    float* outp = g_c[which];
    #pragma unroll
    for (int i=0;i<4;i++){
        int n = tid + i*256;
        int h = n >> 6, d = n & 63;
        outp[(((size_t)(bb*NH + h))*NS + s)*ND + d] = ln[i]*scale;
    }
}

// ============ per-head QKV projection (tf32 tensor cores) ============
#define QPA 68    // 64 + 4 pad
__global__ void qkv_tf32_kernel(const float* __restrict__ in_w,
                                const float* __restrict__ in_b, int which) {
    extern __shared__ __align__(16) float sm[];
    float* Xq  = sm;                 // [s][d] 64*68
    float* Xkv = sm + 64*QPA;
    float* Wsm = sm + 2*64*QPA;      // [e][d]
    int bh = blockIdx.y;
    int h = bh & (NH-1);
    int s0 = blockIdx.x * 64;
    int tid = threadIdx.x;
    int wid = tid >> 5, lane = tid & 31;
    int wm = wid >> 1, wn = wid & 1;
    int g = lane >> 2, t = lane & 3;
    int fr0 = wm*16 + g;
    int lr = tid >> 4;             // 0..15
    int lc = (tid & 15) * 4;       // 0..60
    const float* qbase  = g_c[which]   + ((size_t)bh*NS + s0)*ND;
    const float* kvbase = g_c[which^1] + ((size_t)bh*NS + s0)*ND;
    #pragma unroll
    for (int i = 0; i < 4; i++) {
        int r = lr + i*16;
        float4 a  = *(const float4*)(qbase  + r*ND + lc);
        float4 kv = *(const float4*)(kvbase + r*ND + lc);
        float* qd = Xq + r*QPA + lc;
        float* kd = Xkv + r*QPA + lc;
        qd[0]=tf32f(a.x);  qd[1]=tf32f(a.y);  qd[2]=tf32f(a.z);  qd[3]=tf32f(a.w);
        kd[0]=tf32f(kv.x); kd[1]=tf32f(kv.y); kd[2]=tf32f(kv.z); kd[3]=tf32f(kv.w);
    }
    __syncthreads();
    unsigned aq[8][4], akv[8][4];
    #pragma unroll
    for (int kc = 0; kc < 8; kc++) {
        const float* qb = Xq  + fr0*QPA + kc*8 + t;
        const float* kb = Xkv + fr0*QPA + kc*8 + t;
        aq[kc][0]=__float_as_uint(qb[0]);        aq[kc][1]=__float_as_uint(qb[8*QPA]);
        aq[kc][2]=__float_as_uint(qb[4]);        aq[kc][3]=__float_as_uint(qb[8*QPA+4]);
        akv[kc][0]=__float_as_uint(kb[0]);       akv[kc][1]=__float_as_uint(kb[8*QPA]);
        akv[kc][2]=__float_as_uint(kb[4]);       akv[kc][3]=__float_as_uint(kb[8*QPA+4]);
    }
    for (int p = 0; p < 3; p++) {
        if (p) __syncthreads();
        const float* wsrc = in_w + ((size_t)h*192 + p*64)*64;   // [e][d]
        #pragma unroll
        for (int i = 0; i < 4; i++) {
            int r = lr + i*16;
            float4 w = *(const float4*)(wsrc + r*64 + lc);
            float* wd = Wsm + r*QPA + lc;
            wd[0]=tf32f(w.x); wd[1]=tf32f(w.y); wd[2]=tf32f(w.z); wd[3]=tf32f(w.w);
        }
        __syncthreads();
        float acc[4][4] = {};
        #pragma unroll
        for (int kc = 0; kc < 8; kc++) {
            const unsigned* a = (p == 0) ? aq[kc] : akv[kc];
            #pragma unroll
            for (int nt = 0; nt < 4; nt++) {
                const float* bb = Wsm + (wn*32 + nt*8 + g)*QPA + kc*8 + t;
                mma_tf32(acc[nt], a, __float_as_uint(bb[0]), __float_as_uint(bb[4]));
            }
        }
        float* dst = (p==0) ? g_q[which] : (p==1) ? g_k[which] : g_v[which];
        float qscale = (p==0) ? 0.125f : 1.f;
        const float* bsrc = in_b + h*192 + p*64;
        #pragma unroll
        for (int nt = 0; nt < 4; nt++) {
            int c = wn*32 + nt*8 + 2*t;
            float bx = bsrc[c], by = bsrc[c+1];
            float* o0 = dst + ((size_t)bh*NS + s0 + fr0)*ND + c;
            float* o1 = dst + ((size_t)bh*NS + s0 + fr0 + 8)*ND + c;
            *(float2*)o0 = make_float2((acc[nt][0]+bx)*qscale, (acc[nt][1]+by)*qscale);
            *(float2*)o1 = make_float2((acc[nt][2]+bx)*qscale, (acc[nt][3]+by)*qscale);
        }
    }
}

// ---------------- flash attention with mma.sync tf32 tensor cores ----------------
#define PAD 76
__global__ void attn_kernel(int which) {
    extern __shared__ __align__(16) float sm[];
    float* qs = sm;
    float* ks = sm + 64*PAD;
    float* vs = sm + 2*64*PAD;
    float* rowm = sm + 3*64*PAD;
    float* rowl = rowm + 64;
    float* rowf = rowl + 64;
    float* ps = qs;

    const float* Q = g_q[which];
    const float* K = g_k[which];
    const float* V = g_v[which];
    float* O = g_o[which];
    int bh = blockIdx.y, q0 = blockIdx.x * 64;
    int tid = threadIdx.x;
    int wid = tid >> 5, lane = tid & 31;
    int wm = wid >> 1, wn = wid & 1;
    int g = lane >> 2, t = lane & 3;
    int fr0 = wm*16 + g;

    {
        int r = tid >> 2, c0 = (tid & 3) * 16;
        const float* src = Q + ((size_t)bh*NS + q0 + r)*ND + c0;
        float* dst = qs + r*PAD + c0;
        #pragma unroll
        for (int i = 0; i < 4; i++) {
            float4 v4 = *(const float4*)(src + i*4);
            dst[i*4+0]=tf32f(v4.x); dst[i*4+1]=tf32f(v4.y);
            dst[i*4+2]=tf32f(v4.z); dst[i*4+3]=tf32f(v4.w);
        }
    }
    if (tid < 64) { rowm[tid] = -1e30f; rowl[tid] = 0.f; }
    __syncthreads();

    unsigned qf[8][4];
    #pragma unroll
    for (int kc = 0; kc < 8; kc++) {
        const float* base = qs + fr0*PAD + kc*8 + t;
        qf[kc][0] = __float_as_uint(base[0]);
        qf[kc][1] = __float_as_uint(base[8*PAD]);
        qf[kc][2] = __float_as_uint(base[4]);
        qf[kc][3] = __float_as_uint(base[8*PAD+4]);
    }
    __syncthreads();

    float of[4][4] = {};
    for (int j0 = 0; j0 < NS; j0 += 64) {
        {
            int r = tid >> 2, c0 = (tid & 3) * 16;
            const float* ksrc = K + ((size_t)bh*NS + j0 + r)*ND + c0;
            const float* vsrc = V + ((size_t)bh*NS + j0 + r)*ND + c0;
            float* kd = ks + r*PAD + c0;
            float* vd = vs + r*PAD + c0;
            #pragma unroll
            for (int i = 0; i < 4; i++) {
                float4 kv = *(const float4*)(ksrc + i*4);
                float4 vv = *(const float4*)(vsrc + i*4);
                kd[i*4+0]=tf32f(kv.x); kd[i*4+1]=tf32f(kv.y);
                kd[i*4+2]=tf32f(kv.z); kd[i*4+3]=tf32f(kv.w);
                vd[i*4+0]=tf32f(vv.x); vd[i*4+1]=tf32f(vv.y);
                vd[i*4+2]=tf32f(vv.z); vd[i*4+3]=tf32f(vv.w);
            }
        }
        __syncthreads();

        float cf[4][4] = {};
        #pragma unroll
        for (int nt = 0; nt < 4; nt++) {
            int nb = wn*32 + nt*8;
            const float* bbase = ks + (nb + g)*PAD;
            #pragma unroll
            for (int kc = 0; kc < 8; kc++) {
                unsigned b0 = __float_as_uint(bbase[kc*8 + t]);
                unsigned b1 = __float_as_uint(bbase[kc*8 + t + 4]);
                mma_tf32(cf[nt], qf[kc], b0, b1);
            }
        }
        #pragma unroll
        for (int nt = 0; nt < 4; nt++) {
            float* p0 = ps + fr0*PAD + wn*32 + nt*8 + 2*t;
            *(float2*)p0 = make_float2(cf[nt][0], cf[nt][1]);
            *(float2*)(p0 + 8*PAD) = make_float2(cf[nt][2], cf[nt][3]);
        }
        __syncthreads();

        {
            int r = tid >> 2, c0 = (tid & 3) * 16;
            float* prow = ps + r*PAD;
            float mx = -1e30f;
            #pragma unroll
            for (int i = 0; i < 16; i++) mx = fmaxf(mx, prow[c0+i]);
            mx = fmaxf(mx, __shfl_xor_sync(0xffffffffu, mx, 1));
            mx = fmaxf(mx, __shfl_xor_sync(0xffffffffu, mx, 2));
            float mold = rowm[r];
            float mnew = fmaxf(mold, mx);
            float fr = __expf(mold - mnew);
            float l = 0.f;
            #pragma unroll
            for (int i = 0; i < 16; i++) {
                float e = __expf(prow[c0+i] - mnew);
                prow[c0+i] = tf32f(e);
                l += e;
            }
            l += __shfl_xor_sync(0xffffffffu, l, 1);
            l += __shfl_xor_sync(0xffffffffu, l, 2);
            if ((tid & 3) == 0) {
                rowl[r] = rowl[r]*fr + l;
                rowm[r] = mnew;
                rowf[r] = fr;
            }
        }
        __syncthreads();

        float f0 = rowf[fr0], f1 = rowf[fr0 + 8];
        #pragma unroll
        for (int nt = 0; nt < 4; nt++) {
            of[nt][0] *= f0; of[nt][1] *= f0;
            of[nt][2] *= f1; of[nt][3] *= f1;
        }

        #pragma unroll
        for (int kc = 0; kc < 8; kc++) {
            const float* pa = ps + fr0*PAD + kc*8 + t;
            unsigned a[4];
            a[0] = __float_as_uint(pa[0]);
            a[1] = __float_as_uint(pa[8*PAD]);
            a[2] = __float_as_uint(pa[4]);
            a[3] = __float_as_uint(pa[8*PAD+4]);
            #pragma unroll
            for (int nt = 0; nt < 4; nt++) {
                int nb = wn*32 + nt*8;
                unsigned b0 = __float_as_uint(vs[(kc*8 + t)*PAD + nb + g]);
                unsigned b1 = __float_as_uint(vs[(kc*8 + t + 4)*PAD + nb + g]);
                mma_tf32(of[nt], a, b0, b1);
            }
        }
        __syncthreads();
    }

    float il0 = 1.f / rowl[fr0];
    float il1 = 1.f / rowl[fr0 + 8];
    #pragma unroll
    for (int nt = 0; nt < 4; nt++) {
        int col = wn*32 + nt*8 + 2*t;
        float* o0 = O + ((size_t)bh*NS + q0 + fr0)*ND + col;
        float* o1 = O + ((size_t)bh*NS + q0 + fr0 + 8)*ND + col;
        *(float2*)o0 = make_float2(of[nt][0]*il0, of[nt][1]*il0);
        *(float2*)o1 = make_float2(of[nt][2]*il1, of[nt][3]*il1);
    }
}

// ============ out projection + residual (tf32 tensor cores) ============
__global__ void outproj_tf32_kernel(const float* __restrict__ out_w,
                                    const float* __restrict__ out_b, int which) {
    __shared__ __align__(16) float Xs[64*QPA];
    __shared__ __align__(16) float Wsm[64*QPA];
    int bh = blockIdx.y, h = bh & (NH-1), s0 = blockIdx.x*64;
    int tid = threadIdx.x;
    int wid = tid >> 5, lane = tid & 31;
    int wm = wid >> 1, wn = wid & 1;
    int g = lane >> 2, t = lane & 3;
    int fr0 = wm*16 + g;
    int lr = tid >> 4, lc = (tid & 15) * 4;
    const float* xbase = g_o[which] + ((size_t)bh*NS + s0)*ND;
    const float* wsrc  = out_w + (size_t)h*64*64;   // [f][e]
    #pragma unroll
    for (int i = 0; i < 4; i++) {
        int r = lr + i*16;
        float4 x = *(const float4*)(xbase + r*ND + lc);
        float4 w = *(const float4*)(wsrc  + r*64 + lc);
        float* xd = Xs + r*QPA + lc;
        float* wd = Wsm + r*QPA + lc;
        xd[0]=tf32f(x.x); xd[1]=tf32f(x.y); xd[2]=tf32f(x.z); xd[3]=tf32f(x.w);
        wd[0]=tf32f(w.x); wd[1]=tf32f(w.y); wd[2]=tf32f(w.z); wd[3]=tf32f(w.w);
    }
    __syncthreads();
    float acc[4][4] = {};
    #pragma unroll
    for (int kc = 0; kc < 8; kc++) {
        const float* ab = Xs + fr0*QPA + kc*8 + t;
        unsigned a[4];
        a[0]=__float_as_uint(ab[0]);  a[1]=__float_as_uint(ab[8*QPA]);
        a[2]=__float_as_uint(ab[4]);  a[3]=__float_as_uint(ab[8*QPA+4]);
        #pragma unroll
        for (int nt = 0; nt < 4; nt++) {
            const float* bb = Wsm + (wn*32 + nt*8 + g)*QPA + kc*8 + t;
            mma_tf32(acc[nt], a, __float_as_uint(bb[0]), __float_as_uint(bb[4]));
        }
    }
    const float* resid = g_c[which];
    int off = which * 64;
    #pragma unroll
    for (int nt = 0; nt < 4; nt++) {
        int c = wn*32 + nt*8 + 2*t;
        float bx = out_b[h*64+c], by = out_b[h*64+c+1];
        int s0r = s0 + fr0, s1r = s0 + fr0 + 8;
        const float* r0 = resid + ((size_t)bh*NS + s0r)*ND + c;
        const float* r1 = resid + ((size_t)bh*NS + s1r)*ND + c;
        float* d0 = g_comb + ((size_t)bh*NS + s0r)*128 + off + c;
        float* d1 = g_comb + ((size_t)bh*NS + s1r)*128 + off + c;
        *(float2*)d0 = make_float2(acc[nt][0]+bx+r0[0], acc[nt][1]+by+r0[1]);
        *(float2*)d1 = make_float2(acc[nt][2]+bx+r1[0], acc[nt][3]+by+r1[1]);
    }
}

// ---------------- final LN over concat dim (128) ----------------
__global__ void final_ln_kernel(const float* __restrict__ hg, const float* __restrict__ hb,
                                float* __restrict__ out) {
    int row = blockIdx.x * 8 + (threadIdx.x >> 5);
    int lane = threadIdx.x & 31;
    const float* x = g_comb + (size_t)row * 128;
    float v[4], sum = 0.f;
    #pragma unroll
    for (int i=0;i<4;i++){ v[i] = x[lane + i*32]; sum += v[i]; }
    #pragma unroll
    for (int o = 16; o > 0; o >>= 1) sum += __shfl_xor_sync(0xffffffffu, sum, o);
    float mu = sum * (1.f/128.f);
    float sq = 0.f;
    #pragma unroll
    for (int i=0;i<4;i++){ float d = v[i]-mu; sq += d*d; }
    #pragma unroll
    for (int o = 16; o > 0; o >>= 1) sq += __shfl_xor_sync(0xffffffffu, sq, o);
    float rstd = rsqrtf(sq*(1.f/128.f) + 1e-5f);
    int h = (row >> 9) & 15;
    #pragma unroll
    for (int i=0;i<4;i++){
        int c = lane + i*32;
        out[(size_t)row*128 + c] = (v[i]-mu)*rstd*hg[h*128+c] + hb[h*128+c];
    }
}

// ---------------- launch ----------------
extern "C" void kernel_launch(void* const* d_in, const int* in_sizes, int n_in,
                              void* d_out, int out_size) {
    const float* image     = (const float*)d_in[0];
    const float* text      = (const float*)d_in[1];
    const float* img_w     = (const float*)d_in[2];
    const float* img_b     = (const float*)d_in[3];
    const float* img_g     = (const float*)d_in[4];
    const float* img_lb    = (const float*)d_in[5];
    const float* txt_w     = (const float*)d_in[6];
    const float* txt_b     = (const float*)d_in[7];
    const float* txt_g     = (const float*)d_in[8];
    const float* txt_lb    = (const float*)d_in[9];
    const float* i2t_in_w  = (const float*)d_in[10];
    const float* i2t_in_b  = (const float*)d_in[11];
    const float* i2t_out_w = (const float*)d_in[12];
    const float* i2t_out_b = (const float*)d_in[13];
    const float* t2i_in_w  = (const float*)d_in[14];
    const float* t2i_in_b  = (const float*)d_in[15];
    const float* t2i_out_w = (const float*)d_in[16];
    const float* t2i_out_b = (const float*)d_in[17];
    const float* hn_g      = (const float*)d_in[18];
    const float* hn_b      = (const float*)d_in[19];
    float* out = (float*)d_out;

    const int ATTN_SMEM = (3*64*PAD + 3*64) * 4;     // 59136 B
    const int QKV_SMEM  = 3*64*QPA*4;                // 52224 B
    static int attrs_set = 0;
    if (!attrs_set) {
        cudaFuncSetAttribute(attn_kernel, cudaFuncAttributeMaxDynamicSharedMemorySize, ATTN_SMEM);
        cudaFuncSetAttribute(qkv_tf32_kernel, cudaFuncAttributeMaxDynamicSharedMemorySize, QKV_SMEM);
        attrs_set = 1;
    }

    dim3 thr(256);
    gemm_tf32_kernel<<<dim3(8,64), thr>>>(image, img_w, img_b, 768, 0);
    gemm_tf32_kernel<<<dim3(8,64), thr>>>(text,  txt_w, txt_b, 512, 1);
    ln_l2_kernel<<<8192, thr>>>(img_g, img_lb, 0);
    ln_l2_kernel<<<8192, thr>>>(txt_g, txt_lb, 1);
    qkv_tf32_kernel<<<dim3(8,256), thr, QKV_SMEM>>>(i2t_in_w, i2t_in_b, 0);
    qkv_tf32_kernel<<<dim3(8,256), thr, QKV_SMEM>>>(t2i_in_w, t2i_in_b, 1);
    attn_kernel<<<dim3(8,256), thr, ATTN_SMEM>>>(0);
    attn_kernel<<<dim3(8,256), thr, ATTN_SMEM>>>(1);
    outproj_tf32_kernel<<<dim3(8,256), thr>>>(i2t_out_w, i2t_out_b, 0);
    outproj_tf32_kernel<<<dim3(8,256), thr>>>(t2i_out_w, t2i_out_b, 1);
    final_ln_kernel<<<16384, thr>>>(hn_g, hn_b, out);
}

// round 10
// speedup vs baseline: 1.0050x; 1.0050x over previous
#include <cuda_runtime.h>
#include <math.h>

#define NB 16
#define NS 512
#define NH 16
#define ND 64
#define NHID 1024
#define NROW (NB*NS)        // 8192
#define NBH (NB*NH)         // 256
#define NTOK (NBH*NS*ND)    // 8388608

// ---------------- scratch (static __device__, allocation-guard safe) ----------------
__device__ __align__(16) float g_proj[2][NROW*NHID];
__device__ __align__(16) float g_c[2][NTOK];           // (B,H,S,D)
__device__ __align__(16) float g_q[2][NTOK];
__device__ __align__(16) float g_k[2][NTOK];
__device__ __align__(16) float g_v[2][NTOK];
__device__ __align__(16) float g_o[2][NTOK];
__device__ __align__(16) float g_comb[NBH*NS*2*ND];    // (B,H,S,128)

// ---------------- tf32 mma helpers ----------------
__device__ __forceinline__ unsigned cvt_tf32(float x) {
    unsigned u; asm("cvt.rna.tf32.f32 %0, %1;" : "=r"(u) : "f"(x)); return u;
}
__device__ __forceinline__ float tf32f(float x) {
    return __uint_as_float(cvt_tf32(x));
}
__device__ __forceinline__ void mma_tf32(float c[4], const unsigned a[4], unsigned b0, unsigned b1) {
    asm("mma.sync.aligned.m16n8k8.row.col.f32.tf32.tf32.f32 "
        "{%0,%1,%2,%3}, {%4,%5,%6,%7}, {%8,%9}, {%0,%1,%2,%3};"
        : "+f"(c[0]), "+f"(c[1]), "+f"(c[2]), "+f"(c[3])
        : "r"(a[0]), "r"(a[1]), "r"(a[2]), "r"(a[3]), "r"(b0), "r"(b1));
}

// ============ big projection GEMM (tf32 tensor cores) ============
// C[M,1024] = A[M,K] @ W[1024,K]^T + bias.  CTA tile 128x128, BK=32.
#define GPA 36    // 32 + 4 pad -> (4g+t) bank-unique fragment gathers
__global__ void gemm_tf32_kernel(const float* __restrict__ A,
                                 const float* __restrict__ W,
                                 const float* __restrict__ bias,
                                 int K, int which) {
    __shared__ __align__(16) float As[128*GPA];
    __shared__ __align__(16) float Ws[128*GPA];
    float* C = g_proj[which];
    int tid = threadIdx.x;
    int wid = tid >> 5, lane = tid & 31;
    int wm = wid >> 1, wn = wid & 1;
    int g = lane >> 2, t = lane & 3;
    int m0 = blockIdx.y * 128, n0 = blockIdx.x * 128;
    int lr = tid >> 3;           // 0..31
    int lc = (tid & 7) * 4;      // 0..28
    float acc[2][8][4] = {};
    for (int k0 = 0; k0 < K; k0 += 32) {
        #pragma unroll
        for (int i = 0; i < 4; i++) {
            int r = lr + i*32;
            float4 av = *(const float4*)(A + (size_t)(m0 + r)*K + k0 + lc);
            float4 wv = *(const float4*)(W + (size_t)(n0 + r)*K + k0 + lc);
            float* ad = As + r*GPA + lc;
            float* wd = Ws + r*GPA + lc;
            ad[0]=tf32f(av.x); ad[1]=tf32f(av.y); ad[2]=tf32f(av.z); ad[3]=tf32f(av.w);
            wd[0]=tf32f(wv.x); wd[1]=tf32f(wv.y); wd[2]=tf32f(wv.z); wd[3]=tf32f(wv.w);
        }
        __syncthreads();
        #pragma unroll
        for (int kc = 0; kc < 4; kc++) {
            unsigned a[2][4];
            #pragma unroll
            for (int mf = 0; mf < 2; mf++) {
                const float* ab = As + (wm*32 + mf*16 + g)*GPA + kc*8 + t;
                a[mf][0] = __float_as_uint(ab[0]);
                a[mf][1] = __float_as_uint(ab[8*GPA]);
                a[mf][2] = __float_as_uint(ab[4]);
                a[mf][3] = __float_as_uint(ab[8*GPA+4]);
            }
            #pragma unroll
            for (int nf = 0; nf < 8; nf++) {
                const float* bb = Ws + (wn*64 + nf*8 + g)*GPA + kc*8 + t;
                unsigned b0 = __float_as_uint(bb[0]);
                unsigned b1 = __float_as_uint(bb[4]);
                mma_tf32(acc[0][nf], a[0], b0, b1);
                mma_tf32(acc[1][nf], a[1], b0, b1);
            }
        }
        __syncthreads();
    }
    #pragma unroll
    for (int mf = 0; mf < 2; mf++) {
        int r0 = m0 + wm*32 + mf*16 + g;
        #pragma unroll
        for (int nf = 0; nf < 8; nf++) {
            int c = n0 + wn*64 + nf*8 + 2*t;
            float bx = bias[c], by = bias[c+1];
            *(float2*)(C + (size_t)r0*NHID + c) =
                make_float2(acc[mf][nf][0] + bx, acc[mf][nf][1] + by);
            *(float2*)(C + (size_t)(r0+8)*NHID + c) =
                make_float2(acc[mf][nf][2] + bx, acc[mf][nf][3] + by);
        }
    }
}

// ---------------- LN + l2-normalize + D^-0.5, writes (B,H,S,D) layout ----------------
__device__ __forceinline__ float breduce256(float v, float* red) {
    #pragma unroll
    for (int o = 16; o > 0; o >>= 1) v += __shfl_xor_sync(0xffffffffu, v, o);
    int tid = threadIdx.x;
    if ((tid & 31) == 0) red[tid >> 5] = v;
    __syncthreads();
    float t = 0.f;
    #pragma unroll
    for (int i = 0; i < 8; i++) t += red[i];
    __syncthreads();
    return t;
}

__global__ void ln_l2_kernel(const float* __restrict__ g, const float* __restrict__ b, int which) {
    __shared__ float red[8];
    int row = blockIdx.x;
    int tid = threadIdx.x;
    const float* y = g_proj[which] + (size_t)row * NHID;
    float v[4], sum = 0.f;
    #pragma unroll
    for (int i=0;i<4;i++){ v[i] = y[tid + i*256]; sum += v[i]; }
    sum = breduce256(sum, red);
    float mu = sum * (1.f/NHID);
    float sq = 0.f;
    #pragma unroll
    for (int i=0;i<4;i++){ float d = v[i]-mu; sq += d*d; }
    sq = breduce256(sq, red);
    float rstd = rsqrtf(sq*(1.f/NHID) + 1e-5f);
    float ln[4], s2 = 0.f;
    #pragma unroll
    for (int i=0;i<4;i++){ int n = tid+i*256; ln[i] = (v[i]-mu)*rstd*g[n] + b[n]; s2 += ln[i]*ln[i]; }
    s2 = breduce256(s2, red);
    float scale = 0.125f / fmaxf(sqrtf(s2), 1e-12f);
    int bb = row >> 9, s = row & 511;
    float* outp = g_c[which];
    #pragma unroll
    for (int i=0;i<4;i++){
        int n = tid + i*256;
        int h = n >> 6, d = n & 63;
        outp[(((size_t)(bb*NH + h))*NS + s)*ND + d] = ln[i]*scale;
    }
}

// ============ per-head QKV projection (tf32 tensor cores) ============
#define QPA 68    // 64 + 4 pad
__global__ void qkv_tf32_kernel(const float* __restrict__ in_w,
                                const float* __restrict__ in_b, int which) {
    extern __shared__ __align__(16) float sm[];
    float* Xq  = sm;                 // [s][d] 64*68
    float* Xkv = sm + 64*QPA;
    float* Wsm = sm + 2*64*QPA;      // [e][d]
    int bh = blockIdx.y;
    int h = bh & (NH-1);
    int s0 = blockIdx.x * 64;
    int tid = threadIdx.x;
    int wid = tid >> 5, lane = tid & 31;
    int wm = wid >> 1, wn = wid & 1;
    int g = lane >> 2, t = lane & 3;
    int fr0 = wm*16 + g;
    int lr = tid >> 4;             // 0..15
    int lc = (tid & 15) * 4;       // 0..60
    const float* qbase  = g_c[which]   + ((size_t)bh*NS + s0)*ND;
    const float* kvbase = g_c[which^1] + ((size_t)bh*NS + s0)*ND;
    #pragma unroll
    for (int i = 0; i < 4; i++) {
        int r = lr + i*16;
        float4 a  = *(const float4*)(qbase  + r*ND + lc);
        float4 kv = *(const float4*)(kvbase + r*ND + lc);
        float* qd = Xq + r*QPA + lc;
        float* kd = Xkv + r*QPA + lc;
        qd[0]=tf32f(a.x);  qd[1]=tf32f(a.y);  qd[2]=tf32f(a.z);  qd[3]=tf32f(a.w);
        kd[0]=tf32f(kv.x); kd[1]=tf32f(kv.y); kd[2]=tf32f(kv.z); kd[3]=tf32f(kv.w);
    }
    __syncthreads();
    unsigned aq[8][4], akv[8][4];
    #pragma unroll
    for (int kc = 0; kc < 8; kc++) {
        const float* qb = Xq  + fr0*QPA + kc*8 + t;
        const float* kb = Xkv + fr0*QPA + kc*8 + t;
        aq[kc][0]=__float_as_uint(qb[0]);        aq[kc][1]=__float_as_uint(qb[8*QPA]);
        aq[kc][2]=__float_as_uint(qb[4]);        aq[kc][3]=__float_as_uint(qb[8*QPA+4]);
        akv[kc][0]=__float_as_uint(kb[0]);       akv[kc][1]=__float_as_uint(kb[8*QPA]);
        akv[kc][2]=__float_as_uint(kb[4]);       akv[kc][3]=__float_as_uint(kb[8*QPA+4]);
    }
    for (int p = 0; p < 3; p++) {
        if (p) __syncthreads();
        const float* wsrc = in_w + ((size_t)h*192 + p*64)*64;   // [e][d]
        #pragma unroll
        for (int i = 0; i < 4; i++) {
            int r = lr + i*16;
            float4 w = *(const float4*)(wsrc + r*64 + lc);
            float* wd = Wsm + r*QPA + lc;
            wd[0]=tf32f(w.x); wd[1]=tf32f(w.y); wd[2]=tf32f(w.z); wd[3]=tf32f(w.w);
        }
        __syncthreads();
        float acc[4][4] = {};
        #pragma unroll
        for (int kc = 0; kc < 8; kc++) {
            const unsigned* a = (p == 0) ? aq[kc] : akv[kc];
            #pragma unroll
            for (int nt = 0; nt < 4; nt++) {
                const float* bb = Wsm + (wn*32 + nt*8 + g)*QPA + kc*8 + t;
                mma_tf32(acc[nt], a, __float_as_uint(bb[0]), __float_as_uint(bb[4]));
            }
        }
        float* dst = (p==0) ? g_q[which] : (p==1) ? g_k[which] : g_v[which];
        float qscale = (p==0) ? 0.125f : 1.f;
        const float* bsrc = in_b + h*192 + p*64;
        #pragma unroll
        for (int nt = 0; nt < 4; nt++) {
            int c = wn*32 + nt*8 + 2*t;
            float bx = bsrc[c], by = bsrc[c+1];
            float* o0 = dst + ((size_t)bh*NS + s0 + fr0)*ND + c;
            float* o1 = dst + ((size_t)bh*NS + s0 + fr0 + 8)*ND + c;
            *(float2*)o0 = make_float2((acc[nt][0]+bx)*qscale, (acc[nt][1]+by)*qscale);
            *(float2*)o1 = make_float2((acc[nt][2]+bx)*qscale, (acc[nt][3]+by)*qscale);
        }
    }
}

// ---------------- flash attention with mma.sync tf32 tensor cores ----------------
#define PAD 76
__global__ void attn_kernel(int which) {
    extern __shared__ __align__(16) float sm[];
    float* qs = sm;
    float* ks = sm + 64*PAD;
    float* vs = sm + 2*64*PAD;
    float* rowm = sm + 3*64*PAD;
    float* rowl = rowm + 64;
    float* rowf = rowl + 64;
    float* ps = qs;

    const float* Q = g_q[which];
    const float* K = g_k[which];
    const float* V = g_v[which];
    float* O = g_o[which];
    int bh = blockIdx.y, q0 = blockIdx.x * 64;
    int tid = threadIdx.x;
    int wid = tid >> 5, lane = tid & 31;
    int wm = wid >> 1, wn = wid & 1;
    int g = lane >> 2, t = lane & 3;
    int fr0 = wm*16 + g;

    {
        int r = tid >> 2, c0 = (tid & 3) * 16;
        const float* src = Q + ((size_t)bh*NS + q0 + r)*ND + c0;
        float* dst = qs + r*PAD + c0;
        #pragma unroll
        for (int i = 0; i < 4; i++) {
            float4 v4 = *(const float4*)(src + i*4);
            dst[i*4+0]=tf32f(v4.x); dst[i*4+1]=tf32f(v4.y);
            dst[i*4+2]=tf32f(v4.z); dst[i*4+3]=tf32f(v4.w);
        }
    }
    if (tid < 64) { rowm[tid] = -1e30f; rowl[tid] = 0.f; }
    __syncthreads();

    unsigned qf[8][4];
    #pragma unroll
    for (int kc = 0; kc < 8; kc++) {
        const float* base = qs + fr0*PAD + kc*8 + t;
        qf[kc][0] = __float_as_uint(base[0]);
        qf[kc][1] = __float_as_uint(base[8*PAD]);
        qf[kc][2] = __float_as_uint(base[4]);
        qf[kc][3] = __float_as_uint(base[8*PAD+4]);
    }
    __syncthreads();

    float of[4][4] = {};
    for (int j0 = 0; j0 < NS; j0 += 64) {
        {
            int r = tid >> 2, c0 = (tid & 3) * 16;
            const float* ksrc = K + ((size_t)bh*NS + j0 + r)*ND + c0;
            const float* vsrc = V + ((size_t)bh*NS + j0 + r)*ND + c0;
            float* kd = ks + r*PAD + c0;
            float* vd = vs + r*PAD + c0;
            #pragma unroll
            for (int i = 0; i < 4; i++) {
                float4 kv = *(const float4*)(ksrc + i*4);
                float4 vv = *(const float4*)(vsrc + i*4);
                kd[i*4+0]=tf32f(kv.x); kd[i*4+1]=tf32f(kv.y);
                kd[i*4+2]=tf32f(kv.z); kd[i*4+3]=tf32f(kv.w);
                vd[i*4+0]=tf32f(vv.x); vd[i*4+1]=tf32f(vv.y);
                vd[i*4+2]=tf32f(vv.z); vd[i*4+3]=tf32f(vv.w);
            }
        }
        __syncthreads();

        float cf[4][4] = {};
        #pragma unroll
        for (int nt = 0; nt < 4; nt++) {
            int nb = wn*32 + nt*8;
            const float* bbase = ks + (nb + g)*PAD;
            #pragma unroll
            for (int kc = 0; kc < 8; kc++) {
                unsigned b0 = __float_as_uint(bbase[kc*8 + t]);
                unsigned b1 = __float_as_uint(bbase[kc*8 + t + 4]);
                mma_tf32(cf[nt], qf[kc], b0, b1);
            }
        }
        #pragma unroll
        for (int nt = 0; nt < 4; nt++) {
            float* p0 = ps + fr0*PAD + wn*32 + nt*8 + 2*t;
            *(float2*)p0 = make_float2(cf[nt][0], cf[nt][1]);
            *(float2*)(p0 + 8*PAD) = make_float2(cf[nt][2], cf[nt][3]);
        }
        __syncthreads();

        {
            int r = tid >> 2, c0 = (tid & 3) * 16;
            float* prow = ps + r*PAD;
            float mx = -1e30f;
            #pragma unroll
            for (int i = 0; i < 16; i++) mx = fmaxf(mx, prow[c0+i]);
            mx = fmaxf(mx, __shfl_xor_sync(0xffffffffu, mx, 1));
            mx = fmaxf(mx, __shfl_xor_sync(0xffffffffu, mx, 2));
            float mold = rowm[r];
            float mnew = fmaxf(mold, mx);
            float fr = __expf(mold - mnew);
            float l = 0.f;
            #pragma unroll
            for (int i = 0; i < 16; i++) {
                float e = __expf(prow[c0+i] - mnew);
                prow[c0+i] = tf32f(e);
                l += e;
            }
            l += __shfl_xor_sync(0xffffffffu, l, 1);
            l += __shfl_xor_sync(0xffffffffu, l, 2);
            if ((tid & 3) == 0) {
                rowl[r] = rowl[r]*fr + l;
                rowm[r] = mnew;
                rowf[r] = fr;
            }
        }
        __syncthreads();

        float f0 = rowf[fr0], f1 = rowf[fr0 + 8];
        #pragma unroll
        for (int nt = 0; nt < 4; nt++) {
            of[nt][0] *= f0; of[nt][1] *= f0;
            of[nt][2] *= f1; of[nt][3] *= f1;
        }

        #pragma unroll
        for (int kc = 0; kc < 8; kc++) {
            const float* pa = ps + fr0*PAD + kc*8 + t;
            unsigned a[4];
            a[0] = __float_as_uint(pa[0]);
            a[1] = __float_as_uint(pa[8*PAD]);
            a[2] = __float_as_uint(pa[4]);
            a[3] = __float_as_uint(pa[8*PAD+4]);
            #pragma unroll
            for (int nt = 0; nt < 4; nt++) {
                int nb = wn*32 + nt*8;
                unsigned b0 = __float_as_uint(vs[(kc*8 + t)*PAD + nb + g]);
                unsigned b1 = __float_as_uint(vs[(kc*8 + t + 4)*PAD + nb + g]);
                mma_tf32(of[nt], a, b0, b1);
            }
        }
        __syncthreads();
    }

    float il0 = 1.f / rowl[fr0];
    float il1 = 1.f / rowl[fr0 + 8];
    #pragma unroll
    for (int nt = 0; nt < 4; nt++) {
        int col = wn*32 + nt*8 + 2*t;
        float* o0 = O + ((size_t)bh*NS + q0 + fr0)*ND + col;
        float* o1 = O + ((size_t)bh*NS + q0 + fr0 + 8)*ND + col;
        *(float2*)o0 = make_float2(of[nt][0]*il0, of[nt][1]*il0);
        *(float2*)o1 = make_float2(of[nt][2]*il1, of[nt][3]*il1);
    }
}

// ============ out projection + residual (tf32 tensor cores) ============
__global__ void outproj_tf32_kernel(const float* __restrict__ out_w,
                                    const float* __restrict__ out_b, int which) {
    __shared__ __align__(16) float Xs[64*QPA];
    __shared__ __align__(16) float Wsm[64*QPA];
    int bh = blockIdx.y, h = bh & (NH-1), s0 = blockIdx.x*64;
    int tid = threadIdx.x;
    int wid = tid >> 5, lane = tid & 31;
    int wm = wid >> 1, wn = wid & 1;
    int g = lane >> 2, t = lane & 3;
    int fr0 = wm*16 + g;
    int lr = tid >> 4, lc = (tid & 15) * 4;
    const float* xbase = g_o[which] + ((size_t)bh*NS + s0)*ND;
    const float* wsrc  = out_w + (size_t)h*64*64;   // [f][e]
    #pragma unroll
    for (int i = 0; i < 4; i++) {
        int r = lr + i*16;
        float4 x = *(const float4*)(xbase + r*ND + lc);
        float4 w = *(const float4*)(wsrc  + r*64 + lc);
        float* xd = Xs + r*QPA + lc;
        float* wd = Wsm + r*QPA + lc;
        xd[0]=tf32f(x.x); xd[1]=tf32f(x.y); xd[2]=tf32f(x.z); xd[3]=tf32f(x.w);
        wd[0]=tf32f(w.x); wd[1]=tf32f(w.y); wd[2]=tf32f(w.z); wd[3]=tf32f(w.w);
    }
    __syncthreads();
    float acc[4][4] = {};
    #pragma unroll
    for (int kc = 0; kc < 8; kc++) {
        const float* ab = Xs + fr0*QPA + kc*8 + t;
        unsigned a[4];
        a[0]=__float_as_uint(ab[0]);  a[1]=__float_as_uint(ab[8*QPA]);
        a[2]=__float_as_uint(ab[4]);  a[3]=__float_as_uint(ab[8*QPA+4]);
        #pragma unroll
        for (int nt = 0; nt < 4; nt++) {
            const float* bb = Wsm + (wn*32 + nt*8 + g)*QPA + kc*8 + t;
            mma_tf32(acc[nt], a, __float_as_uint(bb[0]), __float_as_uint(bb[4]));
        }
    }
    const float* resid = g_c[which];
    int off = which * 64;
    #pragma unroll
    for (int nt = 0; nt < 4; nt++) {
        int c = wn*32 + nt*8 + 2*t;
        float bx = out_b[h*64+c], by = out_b[h*64+c+1];
        int s0r = s0 + fr0, s1r = s0 + fr0 + 8;
        const float* r0 = resid + ((size_t)bh*NS + s0r)*ND + c;
        const float* r1 = resid + ((size_t)bh*NS + s1r)*ND + c;
        float* d0 = g_comb + ((size_t)bh*NS + s0r)*128 + off + c;
        float* d1 = g_comb + ((size_t)bh*NS + s1r)*128 + off + c;
        *(float2*)d0 = make_float2(acc[nt][0]+bx+r0[0], acc[nt][1]+by+r0[1]);
        *(float2*)d1 = make_float2(acc[nt][2]+bx+r1[0], acc[nt][3]+by+r1[1]);
    }
}

// ---------------- final LN over concat dim (128) ----------------
__global__ void final_ln_kernel(const float* __restrict__ hg, const float* __restrict__ hb,
                                float* __restrict__ out) {
    int row = blockIdx.x * 8 + (threadIdx.x >> 5);
    int lane = threadIdx.x & 31;
    const float* x = g_comb + (size_t)row * 128;
    float v[4], sum = 0.f;
    #pragma unroll
    for (int i=0;i<4;i++){ v[i] = x[lane + i*32]; sum += v[i]; }
    #pragma unroll
    for (int o = 16; o > 0; o >>= 1) sum += __shfl_xor_sync(0xffffffffu, sum, o);
    float mu = sum * (1.f/128.f);
    float sq = 0.f;
    #pragma unroll
    for (int i=0;i<4;i++){ float d = v[i]-mu; sq += d*d; }
    #pragma unroll
    for (int o = 16; o > 0; o >>= 1) sq += __shfl_xor_sync(0xffffffffu, sq, o);
    float rstd = rsqrtf(sq*(1.f/128.f) + 1e-5f);
    int h = (row >> 9) & 15;
    #pragma unroll
    for (int i=0;i<4;i++){
        int c = lane + i*32;
        out[(size_t)row*128 + c] = (v[i]-mu)*rstd*hg[h*128+c] + hb[h*128+c];
    }
}

// ---------------- launch ----------------
extern "C" void kernel_launch(void* const* d_in, const int* in_sizes, int n_in,
                              void* d_out, int out_size) {
    const float* image     = (const float*)d_in[0];
    const float* text      = (const float*)d_in[1];
    const float* img_w     = (const float*)d_in[2];
    const float* img_b     = (const float*)d_in[3];
    const float* img_g     = (const float*)d_in[4];
    const float* img_lb    = (const float*)d_in[5];
    const float* txt_w     = (const float*)d_in[6];
    const float* txt_b     = (const float*)d_in[7];
    const float* txt_g     = (const float*)d_in[8];
    const float* txt_lb    = (const float*)d_in[9];
    const float* i2t_in_w  = (const float*)d_in[10];
    const float* i2t_in_b  = (const float*)d_in[11];
    const float* i2t_out_w = (const float*)d_in[12];
    const float* i2t_out_b = (const float*)d_in[13];
    const float* t2i_in_w  = (const float*)d_in[14];
    const float* t2i_in_b  = (const float*)d_in[15];
    const float* t2i_out_w = (const float*)d_in[16];
    const float* t2i_out_b = (const float*)d_in[17];
    const float* hn_g      = (const float*)d_in[18];
    const float* hn_b      = (const float*)d_in[19];
    float* out = (float*)d_out;

    const int ATTN_SMEM = (3*64*PAD + 3*64) * 4;     // 59136 B
    const int QKV_SMEM  = 3*64*QPA*4;                // 52224 B
    static int attrs_set = 0;
    if (!attrs_set) {
        cudaFuncSetAttribute(attn_kernel, cudaFuncAttributeMaxDynamicSharedMemorySize, ATTN_SMEM);
        cudaFuncSetAttribute(qkv_tf32_kernel, cudaFuncAttributeMaxDynamicSharedMemorySize, QKV_SMEM);
        attrs_set = 1;
    }

    dim3 thr(256);
    gemm_tf32_kernel<<<dim3(8,64), thr>>>(image, img_w, img_b, 768, 0);
    gemm_tf32_kernel<<<dim3(8,64), thr>>>(text,  txt_w, txt_b, 512, 1);
    ln_l2_kernel<<<8192, thr>>>(img_g, img_lb, 0);
    ln_l2_kernel<<<8192, thr>>>(txt_g, txt_lb, 1);
    qkv_tf32_kernel<<<dim3(8,256), thr, QKV_SMEM>>>(i2t_in_w, i2t_in_b, 0);
    qkv_tf32_kernel<<<dim3(8,256), thr, QKV_SMEM>>>(t2i_in_w, t2i_in_b, 1);
    attn_kernel<<<dim3(8,256), thr, ATTN_SMEM>>>(0);
    attn_kernel<<<dim3(8,256), thr, ATTN_SMEM>>>(1);
    outproj_tf32_kernel<<<dim3(8,256), thr>>>(i2t_out_w, i2t_out_b, 0);
    outproj_tf32_kernel<<<dim3(8,256), thr>>>(t2i_out_w, t2i_out_b, 1);
    final_ln_kernel<<<16384, thr>>>(hn_g, hn_b, out);
}

// round 11
// speedup vs baseline: 1.3533x; 1.3465x over previous
#include <cuda_runtime.h>
#include <math.h>

#define NB 16
#define NS 512
#define NH 16
#define ND 64
#define NHID 1024
#define NROW (NB*NS)        // 8192
#define NBH (NB*NH)         // 256
#define NTOK (NBH*NS*ND)    // 8388608

// ---------------- scratch (static __device__, allocation-guard safe) ----------------
__device__ __align__(16) float g_proj[2][NROW*NHID];
__device__ __align__(16) float g_c[2][NTOK];           // (B,H,S,D)
__device__ __align__(16) float g_q[2][NTOK];
__device__ __align__(16) float g_k[2][NTOK];
__device__ __align__(16) float g_v[2][NTOK];
__device__ __align__(16) float g_o[2][NTOK];
__device__ __align__(16) float g_comb[NBH*NS*2*ND];    // (B,H,S,128)

// ---------------- tf32 mma helpers ----------------
__device__ __forceinline__ unsigned cvt_tf32(float x) {
    unsigned u; asm("cvt.rna.tf32.f32 %0, %1;" : "=r"(u) : "f"(x)); return u;
}
__device__ __forceinline__ float tf32f(float x) {
    return __uint_as_float(cvt_tf32(x));
}
__device__ __forceinline__ void mma_tf32(float c[4], const unsigned a[4], unsigned b0, unsigned b1) {
    asm("mma.sync.aligned.m16n8k8.row.col.f32.tf32.tf32.f32 "
        "{%0,%1,%2,%3}, {%4,%5,%6,%7}, {%8,%9}, {%0,%1,%2,%3};"
        : "+f"(c[0]), "+f"(c[1]), "+f"(c[2]), "+f"(c[3])
        : "r"(a[0]), "r"(a[1]), "r"(a[2]), "r"(a[3]), "r"(b0), "r"(b1));
}

// ============ big projection GEMM (tf32 tensor cores) ============
#define GPA 36
__global__ void gemm_tf32_kernel(const float* __restrict__ A,
                                 const float* __restrict__ W,
                                 const float* __restrict__ bias,
                                 int K, int which) {
    __shared__ __align__(16) float As[128*GPA];
    __shared__ __align__(16) float Ws[128*GPA];
    float* C = g_proj[which];
    int tid = threadIdx.x;
    int wid = tid >> 5, lane = tid & 31;
    int wm = wid >> 1, wn = wid & 1;
    int g = lane >> 2, t = lane & 3;
    int m0 = blockIdx.y * 128, n0 = blockIdx.x * 128;
    int lr = tid >> 3;
    int lc = (tid & 7) * 4;
    float acc[2][8][4] = {};
    for (int k0 = 0; k0 < K; k0 += 32) {
        #pragma unroll
        for (int i = 0; i < 4; i++) {
            int r = lr + i*32;
            float4 av = *(const float4*)(A + (size_t)(m0 + r)*K + k0 + lc);
            float4 wv = *(const float4*)(W + (size_t)(n0 + r)*K + k0 + lc);
            float* ad = As + r*GPA + lc;
            float* wd = Ws + r*GPA + lc;
            ad[0]=tf32f(av.x); ad[1]=tf32f(av.y); ad[2]=tf32f(av.z); ad[3]=tf32f(av.w);
            wd[0]=tf32f(wv.x); wd[1]=tf32f(wv.y); wd[2]=tf32f(wv.z); wd[3]=tf32f(wv.w);
        }
        __syncthreads();
        #pragma unroll
        for (int kc = 0; kc < 4; kc++) {
            unsigned a[2][4];
            #pragma unroll
            for (int mf = 0; mf < 2; mf++) {
                const float* ab = As + (wm*32 + mf*16 + g)*GPA + kc*8 + t;
                a[mf][0] = __float_as_uint(ab[0]);
                a[mf][1] = __float_as_uint(ab[8*GPA]);
                a[mf][2] = __float_as_uint(ab[4]);
                a[mf][3] = __float_as_uint(ab[8*GPA+4]);
            }
            #pragma unroll
            for (int nf = 0; nf < 8; nf++) {
                const float* bb = Ws + (wn*64 + nf*8 + g)*GPA + kc*8 + t;
                unsigned b0 = __float_as_uint(bb[0]);
                unsigned b1 = __float_as_uint(bb[4]);
                mma_tf32(acc[0][nf], a[0], b0, b1);
                mma_tf32(acc[1][nf], a[1], b0, b1);
            }
        }
        __syncthreads();
    }
    #pragma unroll
    for (int mf = 0; mf < 2; mf++) {
        int r0 = m0 + wm*32 + mf*16 + g;
        #pragma unroll
        for (int nf = 0; nf < 8; nf++) {
            int c = n0 + wn*64 + nf*8 + 2*t;
            float bx = bias[c], by = bias[c+1];
            *(float2*)(C + (size_t)r0*NHID + c) =
                make_float2(acc[mf][nf][0] + bx, acc[mf][nf][1] + by);
            *(float2*)(C + (size_t)(r0+8)*NHID + c) =
                make_float2(acc[mf][nf][2] + bx, acc[mf][nf][3] + by);
        }
    }
}

// ---------------- LN + l2-normalize + D^-0.5 (merged both directions) ----------------
__device__ __forceinline__ float breduce256(float v, float* red) {
    #pragma unroll
    for (int o = 16; o > 0; o >>= 1) v += __shfl_xor_sync(0xffffffffu, v, o);
    int tid = threadIdx.x;
    if ((tid & 31) == 0) red[tid >> 5] = v;
    __syncthreads();
    float t = 0.f;
    #pragma unroll
    for (int i = 0; i < 8; i++) t += red[i];
    __syncthreads();
    return t;
}

__global__ void ln_l2_kernel(const float* __restrict__ g0, const float* __restrict__ b0,
                             const float* __restrict__ g1, const float* __restrict__ b1) {
    __shared__ float red[8];
    int which = blockIdx.y;
    const float* g = which ? g1 : g0;
    const float* b = which ? b1 : b0;
    int row = blockIdx.x;
    int tid = threadIdx.x;
    const float* y = g_proj[which] + (size_t)row * NHID;
    float v[4], sum = 0.f;
    #pragma unroll
    for (int i=0;i<4;i++){ v[i] = y[tid + i*256]; sum += v[i]; }
    sum = breduce256(sum, red);
    float mu = sum * (1.f/NHID);
    float sq = 0.f;
    #pragma unroll
    for (int i=0;i<4;i++){ float d = v[i]-mu; sq += d*d; }
    sq = breduce256(sq, red);
    float rstd = rsqrtf(sq*(1.f/NHID) + 1e-5f);
    float ln[4], s2 = 0.f;
    #pragma unroll
    for (int i=0;i<4;i++){ int n = tid+i*256; ln[i] = (v[i]-mu)*rstd*g[n] + b[n]; s2 += ln[i]*ln[i]; }
    s2 = breduce256(s2, red);
    float scale = 0.125f / fmaxf(sqrtf(s2), 1e-12f);
    int bb = row >> 9, s = row & 511;
    float* outp = g_c[which];
    #pragma unroll
    for (int i=0;i<4;i++){
        int n = tid + i*256;
        int h = n >> 6, d = n & 63;
        outp[(((size_t)(bb*NH + h))*NS + s)*ND + d] = ln[i]*scale;
    }
}

// ============ per-head QKV projection (merged both directions) ============
#define QPA 68
__global__ void qkv_tf32_kernel(const float* __restrict__ w_i2t, const float* __restrict__ b_i2t,
                                const float* __restrict__ w_t2i, const float* __restrict__ b_t2i) {
    extern __shared__ __align__(16) float sm[];
    float* Xq  = sm;
    float* Xkv = sm + 64*QPA;
    float* Wsm = sm + 2*64*QPA;
    int which = blockIdx.z;
    const float* in_w = which ? w_t2i : w_i2t;
    const float* in_b = which ? b_t2i : b_i2t;
    int bh = blockIdx.y;
    int h = bh & (NH-1);
    int s0 = blockIdx.x * 64;
    int tid = threadIdx.x;
    int wid = tid >> 5, lane = tid & 31;
    int wm = wid >> 1, wn = wid & 1;
    int g = lane >> 2, t = lane & 3;
    int fr0 = wm*16 + g;
    int lr = tid >> 4;
    int lc = (tid & 15) * 4;
    const float* qbase  = g_c[which]   + ((size_t)bh*NS + s0)*ND;
    const float* kvbase = g_c[which^1] + ((size_t)bh*NS + s0)*ND;
    #pragma unroll
    for (int i = 0; i < 4; i++) {
        int r = lr + i*16;
        float4 a  = *(const float4*)(qbase  + r*ND + lc);
        float4 kv = *(const float4*)(kvbase + r*ND + lc);
        float* qd = Xq + r*QPA + lc;
        float* kd = Xkv + r*QPA + lc;
        qd[0]=tf32f(a.x);  qd[1]=tf32f(a.y);  qd[2]=tf32f(a.z);  qd[3]=tf32f(a.w);
        kd[0]=tf32f(kv.x); kd[1]=tf32f(kv.y); kd[2]=tf32f(kv.z); kd[3]=tf32f(kv.w);
    }
    __syncthreads();
    unsigned aq[8][4], akv[8][4];
    #pragma unroll
    for (int kc = 0; kc < 8; kc++) {
        const float* qb = Xq  + fr0*QPA + kc*8 + t;
        const float* kb = Xkv + fr0*QPA + kc*8 + t;
        aq[kc][0]=__float_as_uint(qb[0]);   aq[kc][1]=__float_as_uint(qb[8*QPA]);
        aq[kc][2]=__float_as_uint(qb[4]);   aq[kc][3]=__float_as_uint(qb[8*QPA+4]);
        akv[kc][0]=__float_as_uint(kb[0]);  akv[kc][1]=__float_as_uint(kb[8*QPA]);
        akv[kc][2]=__float_as_uint(kb[4]);  akv[kc][3]=__float_as_uint(kb[8*QPA+4]);
    }
    for (int p = 0; p < 3; p++) {
        if (p) __syncthreads();
        const float* wsrc = in_w + ((size_t)h*192 + p*64)*64;
        #pragma unroll
        for (int i = 0; i < 4; i++) {
            int r = lr + i*16;
            float4 w = *(const float4*)(wsrc + r*64 + lc);
            float* wd = Wsm + r*QPA + lc;
            wd[0]=tf32f(w.x); wd[1]=tf32f(w.y); wd[2]=tf32f(w.z); wd[3]=tf32f(w.w);
        }
        __syncthreads();
        float acc[4][4] = {};
        #pragma unroll
        for (int kc = 0; kc < 8; kc++) {
            const unsigned* a = (p == 0) ? aq[kc] : akv[kc];
            #pragma unroll
            for (int nt = 0; nt < 4; nt++) {
                const float* bb = Wsm + (wn*32 + nt*8 + g)*QPA + kc*8 + t;
                mma_tf32(acc[nt], a, __float_as_uint(bb[0]), __float_as_uint(bb[4]));
            }
        }
        float* dst = (p==0) ? g_q[which] : (p==1) ? g_k[which] : g_v[which];
        float qscale = (p==0) ? 0.125f : 1.f;
        const float* bsrc = in_b + h*192 + p*64;
        #pragma unroll
        for (int nt = 0; nt < 4; nt++) {
            int c = wn*32 + nt*8 + 2*t;
            float bx = bsrc[c], by = bsrc[c+1];
            float* o0 = dst + ((size_t)bh*NS + s0 + fr0)*ND + c;
            float* o1 = dst + ((size_t)bh*NS + s0 + fr0 + 8)*ND + c;
            *(float2*)o0 = make_float2((acc[nt][0]+bx)*qscale, (acc[nt][1]+by)*qscale);
            *(float2*)o1 = make_float2((acc[nt][2]+bx)*qscale, (acc[nt][3]+by)*qscale);
        }
    }
}

// ============ flash attention v2: 128-query tile, register softmax ============
// 8 warps; warp w owns rows [w*16, w*16+16). All softmax state in registers.
#define KPAD 68   // 68 mod 32 = 4  -> K frag (4g+t) bank-unique
#define VPAD 72   // 72 mod 32 = 8  -> V frag (8t+g) bank-unique
__global__ void __launch_bounds__(256, 2) attn_kernel() {
    __shared__ __align__(16) float ks[64*KPAD];
    __shared__ __align__(16) float vs[64*VPAD];
    int which = blockIdx.z;
    const float* Q = g_q[which];
    const float* K = g_k[which];
    const float* V = g_v[which];
    float* O = g_o[which];
    int bh = blockIdx.y;
    int q0 = blockIdx.x * 128;
    int tid = threadIdx.x, wid = tid >> 5, lane = tid & 31;
    int g = lane >> 2, t = lane & 3;

    // ---- stage Q (128 x 64, tf32) into ks(rows 0-63) / vs(rows 64-127) ----
    {
        int r = tid >> 1;
        int c0 = (tid & 1) * 32;
        const float* src = Q + ((size_t)bh*NS + q0 + r)*ND + c0;
        float* dst = (r < 64) ? (ks + r*KPAD + c0) : (vs + (r-64)*VPAD + c0);
        #pragma unroll
        for (int i = 0; i < 8; i++) {
            float4 v4 = *(const float4*)(src + i*4);
            dst[i*4+0]=tf32f(v4.x); dst[i*4+1]=tf32f(v4.y);
            dst[i*4+2]=tf32f(v4.z); dst[i*4+3]=tf32f(v4.w);
        }
    }
    __syncthreads();
    unsigned qf[8][4];
    {
        int rq = wid*16 + g;
        const float* base = (rq < 64) ? (ks + rq*KPAD) : (vs + (rq-64)*VPAD);
        int stride = (rq < 64) ? KPAD : VPAD;
        #pragma unroll
        for (int kc = 0; kc < 8; kc++) {
            qf[kc][0] = __float_as_uint(base[kc*8 + t]);
            qf[kc][1] = __float_as_uint(base[8*stride + kc*8 + t]);
            qf[kc][2] = __float_as_uint(base[kc*8 + t + 4]);
            qf[kc][3] = __float_as_uint(base[8*stride + kc*8 + t + 4]);
        }
    }
    __syncthreads();

    float of[8][4] = {};
    float m0 = -1e30f, m1 = -1e30f, l0 = 0.f, l1 = 0.f;

    for (int j0 = 0; j0 < NS; j0 += 64) {
        // ---- stage K,V tile (64 x 64 each, tf32) ----
        {
            int r = tid >> 2, c0 = (tid & 3) * 16;
            const float* ksrc = K + ((size_t)bh*NS + j0 + r)*ND + c0;
            const float* vsrc = V + ((size_t)bh*NS + j0 + r)*ND + c0;
            float* kd = ks + r*KPAD + c0;
            float* vd = vs + r*VPAD + c0;
            #pragma unroll
            for (int i = 0; i < 4; i++) {
                float4 kv = *(const float4*)(ksrc + i*4);
                float4 vv = *(const float4*)(vsrc + i*4);
                kd[i*4+0]=tf32f(kv.x); kd[i*4+1]=tf32f(kv.y);
                kd[i*4+2]=tf32f(kv.z); kd[i*4+3]=tf32f(kv.w);
                vd[i*4+0]=tf32f(vv.x); vd[i*4+1]=tf32f(vv.y);
                vd[i*4+2]=tf32f(vv.z); vd[i*4+3]=tf32f(vv.w);
            }
        }
        __syncthreads();

        // ---- S = Q @ K^T : warp covers 16 rows x all 64 keys ----
        float s[8][4] = {};
        #pragma unroll
        for (int nt = 0; nt < 8; nt++) {
            const float* bb = ks + (nt*8 + g)*KPAD;
            #pragma unroll
            for (int kc = 0; kc < 8; kc++) {
                unsigned b0 = __float_as_uint(bb[kc*8 + t]);
                unsigned b1 = __float_as_uint(bb[kc*8 + t + 4]);
                mma_tf32(s[nt], qf[kc], b0, b1);
            }
        }

        // ---- register online softmax (rows r0=w*16+g, r1=r0+8) ----
        float mx0 = -1e30f, mx1 = -1e30f;
        #pragma unroll
        for (int nt = 0; nt < 8; nt++) {
            mx0 = fmaxf(mx0, fmaxf(s[nt][0], s[nt][1]));
            mx1 = fmaxf(mx1, fmaxf(s[nt][2], s[nt][3]));
        }
        mx0 = fmaxf(mx0, __shfl_xor_sync(0xffffffffu, mx0, 1));
        mx0 = fmaxf(mx0, __shfl_xor_sync(0xffffffffu, mx0, 2));
        mx1 = fmaxf(mx1, __shfl_xor_sync(0xffffffffu, mx1, 1));
        mx1 = fmaxf(mx1, __shfl_xor_sync(0xffffffffu, mx1, 2));
        float mn0 = fmaxf(m0, mx0), mn1 = fmaxf(m1, mx1);
        float f0 = __expf(m0 - mn0), f1 = __expf(m1 - mn1);
        float sum0 = 0.f, sum1 = 0.f;
        #pragma unroll
        for (int nt = 0; nt < 8; nt++) {
            float e0 = __expf(s[nt][0] - mn0);
            float e1 = __expf(s[nt][1] - mn0);
            float e2 = __expf(s[nt][2] - mn1);
            float e3 = __expf(s[nt][3] - mn1);
            sum0 += e0 + e1; sum1 += e2 + e3;
            s[nt][0] = tf32f(e0); s[nt][1] = tf32f(e1);
            s[nt][2] = tf32f(e2); s[nt][3] = tf32f(e3);
        }
        sum0 += __shfl_xor_sync(0xffffffffu, sum0, 1);
        sum0 += __shfl_xor_sync(0xffffffffu, sum0, 2);
        sum1 += __shfl_xor_sync(0xffffffffu, sum1, 1);
        sum1 += __shfl_xor_sync(0xffffffffu, sum1, 2);
        l0 = l0*f0 + sum0; l1 = l1*f1 + sum1;
        m0 = mn0; m1 = mn1;
        #pragma unroll
        for (int nt = 0; nt < 8; nt++) {
            of[nt][0] *= f0; of[nt][1] *= f0;
            of[nt][2] *= f1; of[nt][3] *= f1;
        }

        // ---- O += P @ V : P C-frag -> A-frag via in-warp shuffles ----
        int src0 = (lane & ~3) | (t >> 1);   // holder of col t   (within g-group)
        int src1 = src0 + 2;                 // holder of col t+4
        bool odd = (t & 1);
        #pragma unroll
        for (int kc = 0; kc < 8; kc++) {
            float v00 = __shfl_sync(0xffffffffu, s[kc][0], src0);
            float v01 = __shfl_sync(0xffffffffu, s[kc][1], src0);
            float v10 = __shfl_sync(0xffffffffu, s[kc][2], src0);
            float v11 = __shfl_sync(0xffffffffu, s[kc][3], src0);
            float w00 = __shfl_sync(0xffffffffu, s[kc][0], src1);
            float w01 = __shfl_sync(0xffffffffu, s[kc][1], src1);
            float w10 = __shfl_sync(0xffffffffu, s[kc][2], src1);
            float w11 = __shfl_sync(0xffffffffu, s[kc][3], src1);
            unsigned a[4];
            a[0] = __float_as_uint(odd ? v01 : v00);   // P[r0][kc*8+t]
            a[1] = __float_as_uint(odd ? v11 : v10);   // P[r1][kc*8+t]
            a[2] = __float_as_uint(odd ? w01 : w00);   // P[r0][kc*8+t+4]
            a[3] = __float_as_uint(odd ? w11 : w10);   // P[r1][kc*8+t+4]
            const float* vb0 = vs + (kc*8 + t)*VPAD + g;
            const float* vb1 = vs + (kc*8 + t + 4)*VPAD + g;
            #pragma unroll
            for (int nt = 0; nt < 8; nt++) {
                unsigned b0 = __float_as_uint(vb0[nt*8]);
                unsigned b1 = __float_as_uint(vb1[nt*8]);
                mma_tf32(of[nt], a, b0, b1);
            }
        }
        __syncthreads();
    }

    // ---- epilogue ----
    float il0 = 1.f / l0, il1 = 1.f / l1;
    int r0 = wid*16 + g;
    #pragma unroll
    for (int nt = 0; nt < 8; nt++) {
        int c = nt*8 + 2*t;
        float* o0 = O + ((size_t)bh*NS + q0 + r0)*ND + c;
        float* o1 = o0 + 8*ND;
        *(float2*)o0 = make_float2(of[nt][0]*il0, of[nt][1]*il0);
        *(float2*)o1 = make_float2(of[nt][2]*il1, of[nt][3]*il1);
    }
}

// ============ out projection + residual (merged both directions) ============
__global__ void outproj_tf32_kernel(const float* __restrict__ w_i2t, const float* __restrict__ b_i2t,
                                    const float* __restrict__ w_t2i, const float* __restrict__ b_t2i) {
    __shared__ __align__(16) float Xs[64*QPA];
    __shared__ __align__(16) float Wsm[64*QPA];
    int which = blockIdx.z;
    const float* out_w = which ? w_t2i : w_i2t;
    const float* out_b = which ? b_t2i : b_i2t;
    int bh = blockIdx.y, h = bh & (NH-1), s0 = blockIdx.x*64;
    int tid = threadIdx.x;
    int wid = tid >> 5, lane = tid & 31;
    int wm = wid >> 1, wn = wid & 1;
    int g = lane >> 2, t = lane & 3;
    int fr0 = wm*16 + g;
    int lr = tid >> 4, lc = (tid & 15) * 4;
    const float* xbase = g_o[which] + ((size_t)bh*NS + s0)*ND;
    const float* wsrc  = out_w + (size_t)h*64*64;
    #pragma unroll
    for (int i = 0; i < 4; i++) {
        int r = lr + i*16;
        float4 x = *(const float4*)(xbase + r*ND + lc);
        float4 w = *(const float4*)(wsrc  + r*64 + lc);
        float* xd = Xs + r*QPA + lc;
        float* wd = Wsm + r*QPA + lc;
        xd[0]=tf32f(x.x); xd[1]=tf32f(x.y); xd[2]=tf32f(x.z); xd[3]=tf32f(x.w);
        wd[0]=tf32f(w.x); wd[1]=tf32f(w.y); wd[2]=tf32f(w.z); wd[3]=tf32f(w.w);
    }
    __syncthreads();
    float acc[4][4] = {};
    #pragma unroll
    for (int kc = 0; kc < 8; kc++) {
        const float* ab = Xs + fr0*QPA + kc*8 + t;
        unsigned a[4];
        a[0]=__float_as_uint(ab[0]);  a[1]=__float_as_uint(ab[8*QPA]);
        a[2]=__float_as_uint(ab[4]);  a[3]=__float_as_uint(ab[8*QPA+4]);
        #pragma unroll
        for (int nt = 0; nt < 4; nt++) {
            const float* bb = Wsm + (wn*32 + nt*8 + g)*QPA + kc*8 + t;
            mma_tf32(acc[nt], a, __float_as_uint(bb[0]), __float_as_uint(bb[4]));
        }
    }
    const float* resid = g_c[which];
    int off = which * 64;
    #pragma unroll
    for (int nt = 0; nt < 4; nt++) {
        int c = wn*32 + nt*8 + 2*t;
        float bx = out_b[h*64+c], by = out_b[h*64+c+1];
        int s0r = s0 + fr0, s1r = s0 + fr0 + 8;
        const float* r0 = resid + ((size_t)bh*NS + s0r)*ND + c;
        const float* r1 = resid + ((size_t)bh*NS + s1r)*ND + c;
        float* d0 = g_comb + ((size_t)bh*NS + s0r)*128 + off + c;
        float* d1 = g_comb + ((size_t)bh*NS + s1r)*128 + off + c;
        *(float2*)d0 = make_float2(acc[nt][0]+bx+r0[0], acc[nt][1]+by+r0[1]);
        *(float2*)d1 = make_float2(acc[nt][2]+bx+r1[0], acc[nt][3]+by+r1[1]);
    }
}

// ---------------- final LN over concat dim (128) ----------------
__global__ void final_ln_kernel(const float* __restrict__ hg, const float* __restrict__ hb,
                                float* __restrict__ out) {
    int row = blockIdx.x * 8 + (threadIdx.x >> 5);
    int lane = threadIdx.x & 31;
    const float* x = g_comb + (size_t)row * 128;
    float v[4], sum = 0.f;
    #pragma unroll
    for (int i=0;i<4;i++){ v[i] = x[lane + i*32]; sum += v[i]; }
    #pragma unroll
    for (int o = 16; o > 0; o >>= 1) sum += __shfl_xor_sync(0xffffffffu, sum, o);
    float mu = sum * (1.f/128.f);
    float sq = 0.f;
    #pragma unroll
    for (int i=0;i<4;i++){ float d = v[i]-mu; sq += d*d; }
    #pragma unroll
    for (int o = 16; o > 0; o >>= 1) sq += __shfl_xor_sync(0xffffffffu, sq, o);
    float rstd = rsqrtf(sq*(1.f/128.f) + 1e-5f);
    int h = (row >> 9) & 15;
    #pragma unroll
    for (int i=0;i<4;i++){
        int c = lane + i*32;
        out[(size_t)row*128 + c] = (v[i]-mu)*rstd*hg[h*128+c] + hb[h*128+c];
    }
}

// ---------------- launch ----------------
extern "C" void kernel_launch(void* const* d_in, const int* in_sizes, int n_in,
                              void* d_out, int out_size) {
    const float* image     = (const float*)d_in[0];
    const float* text      = (const float*)d_in[1];
    const float* img_w     = (const float*)d_in[2];
    const float* img_b     = (const float*)d_in[3];
    const float* img_g     = (const float*)d_in[4];
    const float* img_lb    = (const float*)d_in[5];
    const float* txt_w     = (const float*)d_in[6];
    const float* txt_b     = (const float*)d_in[7];
    const float* txt_g     = (const float*)d_in[8];
    const float* txt_lb    = (const float*)d_in[9];
    const float* i2t_in_w  = (const float*)d_in[10];
    const float* i2t_in_b  = (const float*)d_in[11];
    const float* i2t_out_w = (const float*)d_in[12];
    const float* i2t_out_b = (const float*)d_in[13];
    const float* t2i_in_w  = (const float*)d_in[14];
    const float* t2i_in_b  = (const float*)d_in[15];
    const float* t2i_out_w = (const float*)d_in[16];
    const float* t2i_out_b = (const float*)d_in[17];
    const float* hn_g      = (const float*)d_in[18];
    const float* hn_b      = (const float*)d_in[19];
    float* out = (float*)d_out;

    const int QKV_SMEM = 3*64*QPA*4;   // 52224 B
    static int attrs_set = 0;
    if (!attrs_set) {
        cudaFuncSetAttribute(qkv_tf32_kernel, cudaFuncAttributeMaxDynamicSharedMemorySize, QKV_SMEM);
        attrs_set = 1;
    }

    dim3 thr(256);
    gemm_tf32_kernel<<<dim3(8,64), thr>>>(image, img_w, img_b, 768, 0);
    gemm_tf32_kernel<<<dim3(8,64), thr>>>(text,  txt_w, txt_b, 512, 1);
    ln_l2_kernel<<<dim3(8192,2), thr>>>(img_g, img_lb, txt_g, txt_lb);
    qkv_tf32_kernel<<<dim3(8,256,2), thr, QKV_SMEM>>>(i2t_in_w, i2t_in_b, t2i_in_w, t2i_in_b);
    attn_kernel<<<dim3(4,256,2), thr>>>();
    outproj_tf32_kernel<<<dim3(8,256,2), thr>>>(i2t_out_w, i2t_out_b, t2i_out_w, t2i_out_b);
    final_ln_kernel<<<16384, thr>>>(hn_g, hn_b, out);
}

// round 12
// speedup vs baseline: 1.3596x; 1.0046x over previous
#include <cuda_runtime.h>
#include <math.h>

#define NB 16
#define NS 512
#define NH 16
#define ND 64
#define NHID 1024
#define NROW (NB*NS)        // 8192
#define NBH (NB*NH)         // 256
#define NTOK (NBH*NS*ND)    // 8388608

// ---------------- scratch (static __device__, allocation-guard safe) ----------------
__device__ __align__(16) float g_proj[2][NROW*NHID];
__device__ __align__(16) float g_c[2][NTOK];           // (B,H,S,D)
__device__ __align__(16) float g_q[2][NTOK];
__device__ __align__(16) float g_k[2][NTOK];
__device__ __align__(16) float g_v[2][NTOK];
__device__ __align__(16) float g_o[2][NTOK];
__device__ __align__(16) float g_comb[NBH*NS*2*ND];    // (B,H,S,128)

// ---------------- tf32 mma helpers ----------------
__device__ __forceinline__ unsigned cvt_tf32(float x) {
    unsigned u; asm("cvt.rna.tf32.f32 %0, %1;" : "=r"(u) : "f"(x)); return u;
}
__device__ __forceinline__ float tf32f(float x) {
    return __uint_as_float(cvt_tf32(x));
}
__device__ __forceinline__ void mma_tf32(float c[4], const unsigned a[4], unsigned b0, unsigned b1) {
    asm("mma.sync.aligned.m16n8k8.row.col.f32.tf32.tf32.f32 "
        "{%0,%1,%2,%3}, {%4,%5,%6,%7}, {%8,%9}, {%0,%1,%2,%3};"
        : "+f"(c[0]), "+f"(c[1]), "+f"(c[2]), "+f"(c[3])
        : "r"(a[0]), "r"(a[1]), "r"(a[2]), "r"(a[3]), "r"(b0), "r"(b1));
}

// ============ big projection GEMM (tf32 tensor cores) ============
#define GPA 36
__global__ void gemm_tf32_kernel(const float* __restrict__ A,
                                 const float* __restrict__ W,
                                 const float* __restrict__ bias,
                                 int K, int which) {
    __shared__ __align__(16) float As[128*GPA];
    __shared__ __align__(16) float Ws[128*GPA];
    float* C = g_proj[which];
    int tid = threadIdx.x;
    int wid = tid >> 5, lane = tid & 31;
    int wm = wid >> 1, wn = wid & 1;
    int g = lane >> 2, t = lane & 3;
    int m0 = blockIdx.y * 128, n0 = blockIdx.x * 128;
    int lr = tid >> 3;
    int lc = (tid & 7) * 4;
    float acc[2][8][4] = {};
    for (int k0 = 0; k0 < K; k0 += 32) {
        #pragma unroll
        for (int i = 0; i < 4; i++) {
            int r = lr + i*32;
            float4 av = *(const float4*)(A + (size_t)(m0 + r)*K + k0 + lc);
            float4 wv = *(const float4*)(W + (size_t)(n0 + r)*K + k0 + lc);
            float* ad = As + r*GPA + lc;
            float* wd = Ws + r*GPA + lc;
            ad[0]=tf32f(av.x); ad[1]=tf32f(av.y); ad[2]=tf32f(av.z); ad[3]=tf32f(av.w);
            wd[0]=tf32f(wv.x); wd[1]=tf32f(wv.y); wd[2]=tf32f(wv.z); wd[3]=tf32f(wv.w);
        }
        __syncthreads();
        #pragma unroll
        for (int kc = 0; kc < 4; kc++) {
            unsigned a[2][4];
            #pragma unroll
            for (int mf = 0; mf < 2; mf++) {
                const float* ab = As + (wm*32 + mf*16 + g)*GPA + kc*8 + t;
                a[mf][0] = __float_as_uint(ab[0]);
                a[mf][1] = __float_as_uint(ab[8*GPA]);
                a[mf][2] = __float_as_uint(ab[4]);
                a[mf][3] = __float_as_uint(ab[8*GPA+4]);
            }
            #pragma unroll
            for (int nf = 0; nf < 8; nf++) {
                const float* bb = Ws + (wn*64 + nf*8 + g)*GPA + kc*8 + t;
                unsigned b0 = __float_as_uint(bb[0]);
                unsigned b1 = __float_as_uint(bb[4]);
                mma_tf32(acc[0][nf], a[0], b0, b1);
                mma_tf32(acc[1][nf], a[1], b0, b1);
            }
        }
        __syncthreads();
    }
    #pragma unroll
    for (int mf = 0; mf < 2; mf++) {
        int r0 = m0 + wm*32 + mf*16 + g;
        #pragma unroll
        for (int nf = 0; nf < 8; nf++) {
            int c = n0 + wn*64 + nf*8 + 2*t;
            float bx = bias[c], by = bias[c+1];
            *(float2*)(C + (size_t)r0*NHID + c) =
                make_float2(acc[mf][nf][0] + bx, acc[mf][nf][1] + by);
            *(float2*)(C + (size_t)(r0+8)*NHID + c) =
                make_float2(acc[mf][nf][2] + bx, acc[mf][nf][3] + by);
        }
    }
}

// ---------------- LN + l2-normalize + D^-0.5 (merged both directions) ----------------
__device__ __forceinline__ float breduce256(float v, float* red) {
    #pragma unroll
    for (int o = 16; o > 0; o >>= 1) v += __shfl_xor_sync(0xffffffffu, v, o);
    int tid = threadIdx.x;
    if ((tid & 31) == 0) red[tid >> 5] = v;
    __syncthreads();
    float t = 0.f;
    #pragma unroll
    for (int i = 0; i < 8; i++) t += red[i];
    __syncthreads();
    return t;
}

__global__ void ln_l2_kernel(const float* __restrict__ g0, const float* __restrict__ b0,
                             const float* __restrict__ g1, const float* __restrict__ b1) {
    __shared__ float red[8];
    int which = blockIdx.y;
    const float* g = which ? g1 : g0;
    const float* b = which ? b1 : b0;
    int row = blockIdx.x;
    int tid = threadIdx.x;
    const float* y = g_proj[which] + (size_t)row * NHID;
    float v[4], sum = 0.f;
    #pragma unroll
    for (int i=0;i<4;i++){ v[i] = y[tid + i*256]; sum += v[i]; }
    sum = breduce256(sum, red);
    float mu = sum * (1.f/NHID);
    float sq = 0.f;
    #pragma unroll
    for (int i=0;i<4;i++){ float d = v[i]-mu; sq += d*d; }
    sq = breduce256(sq, red);
    float rstd = rsqrtf(sq*(1.f/NHID) + 1e-5f);
    float ln[4], s2 = 0.f;
    #pragma unroll
    for (int i=0;i<4;i++){ int n = tid+i*256; ln[i] = (v[i]-mu)*rstd*g[n] + b[n]; s2 += ln[i]*ln[i]; }
    s2 = breduce256(s2, red);
    float scale = 0.125f / fmaxf(sqrtf(s2), 1e-12f);
    int bb = row >> 9, s = row & 511;
    float* outp = g_c[which];
    #pragma unroll
    for (int i=0;i<4;i++){
        int n = tid + i*256;
        int h = n >> 6, d = n & 63;
        outp[(((size_t)(bb*NH + h))*NS + s)*ND + d] = ln[i]*scale;
    }
}

// ============ per-head QKV projection (merged both directions) ============
#define QPA 68
__global__ void qkv_tf32_kernel(const float* __restrict__ w_i2t, const float* __restrict__ b_i2t,
                                const float* __restrict__ w_t2i, const float* __restrict__ b_t2i) {
    extern __shared__ __align__(16) float sm[];
    float* Xq  = sm;
    float* Xkv = sm + 64*QPA;
    float* Wsm = sm + 2*64*QPA;
    int which = blockIdx.z;
    const float* in_w = which ? w_t2i : w_i2t;
    const float* in_b = which ? b_t2i : b_i2t;
    int bh = blockIdx.y;
    int h = bh & (NH-1);
    int s0 = blockIdx.x * 64;
    int tid = threadIdx.x;
    int wid = tid >> 5, lane = tid & 31;
    int wm = wid >> 1, wn = wid & 1;
    int g = lane >> 2, t = lane & 3;
    int fr0 = wm*16 + g;
    int lr = tid >> 4;
    int lc = (tid & 15) * 4;
    const float* qbase  = g_c[which]   + ((size_t)bh*NS + s0)*ND;
    const float* kvbase = g_c[which^1] + ((size_t)bh*NS + s0)*ND;
    #pragma unroll
    for (int i = 0; i < 4; i++) {
        int r = lr + i*16;
        float4 a  = *(const float4*)(qbase  + r*ND + lc);
        float4 kv = *(const float4*)(kvbase + r*ND + lc);
        float* qd = Xq + r*QPA + lc;
        float* kd = Xkv + r*QPA + lc;
        qd[0]=tf32f(a.x);  qd[1]=tf32f(a.y);  qd[2]=tf32f(a.z);  qd[3]=tf32f(a.w);
        kd[0]=tf32f(kv.x); kd[1]=tf32f(kv.y); kd[2]=tf32f(kv.z); kd[3]=tf32f(kv.w);
    }
    __syncthreads();
    unsigned aq[8][4], akv[8][4];
    #pragma unroll
    for (int kc = 0; kc < 8; kc++) {
        const float* qb = Xq  + fr0*QPA + kc*8 + t;
        const float* kb = Xkv + fr0*QPA + kc*8 + t;
        aq[kc][0]=__float_as_uint(qb[0]);   aq[kc][1]=__float_as_uint(qb[8*QPA]);
        aq[kc][2]=__float_as_uint(qb[4]);   aq[kc][3]=__float_as_uint(qb[8*QPA+4]);
        akv[kc][0]=__float_as_uint(kb[0]);  akv[kc][1]=__float_as_uint(kb[8*QPA]);
        akv[kc][2]=__float_as_uint(kb[4]);  akv[kc][3]=__float_as_uint(kb[8*QPA+4]);
    }
    for (int p = 0; p < 3; p++) {
        if (p) __syncthreads();
        const float* wsrc = in_w + ((size_t)h*192 + p*64)*64;
        #pragma unroll
        for (int i = 0; i < 4; i++) {
            int r = lr + i*16;
            float4 w = *(const float4*)(wsrc + r*64 + lc);
            float* wd = Wsm + r*QPA + lc;
            wd[0]=tf32f(w.x); wd[1]=tf32f(w.y); wd[2]=tf32f(w.z); wd[3]=tf32f(w.w);
        }
        __syncthreads();
        float acc[4][4] = {};
        #pragma unroll
        for (int kc = 0; kc < 8; kc++) {
            const unsigned* a = (p == 0) ? aq[kc] : akv[kc];
            #pragma unroll
            for (int nt = 0; nt < 4; nt++) {
                const float* bb = Wsm + (wn*32 + nt*8 + g)*QPA + kc*8 + t;
                mma_tf32(acc[nt], a, __float_as_uint(bb[0]), __float_as_uint(bb[4]));
            }
        }
        float* dst = (p==0) ? g_q[which] : (p==1) ? g_k[which] : g_v[which];
        float qscale = (p==0) ? 0.125f : 1.f;
        const float* bsrc = in_b + h*192 + p*64;
        #pragma unroll
        for (int nt = 0; nt < 4; nt++) {
            int c = wn*32 + nt*8 + 2*t;
            float bx = bsrc[c], by = bsrc[c+1];
            float* o0 = dst + ((size_t)bh*NS + s0 + fr0)*ND + c;
            float* o1 = dst + ((size_t)bh*NS + s0 + fr0 + 8)*ND + c;
            *(float2*)o0 = make_float2((acc[nt][0]+bx)*qscale, (acc[nt][1]+by)*qscale);
            *(float2*)o1 = make_float2((acc[nt][2]+bx)*qscale, (acc[nt][3]+by)*qscale);
        }
    }
}

// ============ flash attention v2: 128-query tile, register softmax ============
// 8 warps; warp w owns rows [w*16, w*16+16). All softmax state in registers.
#define KPAD 68   // 68 mod 32 = 4  -> K frag (4g+t) bank-unique
#define VPAD 72   // 72 mod 32 = 8  -> V frag (8t+g) bank-unique
__global__ void __launch_bounds__(256, 2) attn_kernel() {
    __shared__ __align__(16) float ks[64*KPAD];
    __shared__ __align__(16) float vs[64*VPAD];
    int which = blockIdx.z;
    const float* Q = g_q[which];
    const float* K = g_k[which];
    const float* V = g_v[which];
    float* O = g_o[which];
    int bh = blockIdx.y;
    int q0 = blockIdx.x * 128;
    int tid = threadIdx.x, wid = tid >> 5, lane = tid & 31;
    int g = lane >> 2, t = lane & 3;

    // ---- stage Q (128 x 64, tf32) into ks(rows 0-63) / vs(rows 64-127) ----
    {
        int r = tid >> 1;
        int c0 = (tid & 1) * 32;
        const float* src = Q + ((size_t)bh*NS + q0 + r)*ND + c0;
        float* dst = (r < 64) ? (ks + r*KPAD + c0) : (vs + (r-64)*VPAD + c0);
        #pragma unroll
        for (int i = 0; i < 8; i++) {
            float4 v4 = *(const float4*)(src + i*4);
            dst[i*4+0]=tf32f(v4.x); dst[i*4+1]=tf32f(v4.y);
            dst[i*4+2]=tf32f(v4.z); dst[i*4+3]=tf32f(v4.w);
        }
    }
    __syncthreads();
    unsigned qf[8][4];
    {
        int rq = wid*16 + g;
        const float* base = (rq < 64) ? (ks + rq*KPAD) : (vs + (rq-64)*VPAD);
        int stride = (rq < 64) ? KPAD : VPAD;
        #pragma unroll
        for (int kc = 0; kc < 8; kc++) {
            qf[kc][0] = __float_as_uint(base[kc*8 + t]);
            qf[kc][1] = __float_as_uint(base[8*stride + kc*8 + t]);
            qf[kc][2] = __float_as_uint(base[kc*8 + t + 4]);
            qf[kc][3] = __float_as_uint(base[8*stride + kc*8 + t + 4]);
        }
    }
    __syncthreads();

    float of[8][4] = {};
    float m0 = -1e30f, m1 = -1e30f, l0 = 0.f, l1 = 0.f;

    for (int j0 = 0; j0 < NS; j0 += 64) {
        // ---- stage K,V tile (64 x 64 each, tf32) ----
        {
            int r = tid >> 2, c0 = (tid & 3) * 16;
            const float* ksrc = K + ((size_t)bh*NS + j0 + r)*ND + c0;
            const float* vsrc = V + ((size_t)bh*NS + j0 + r)*ND + c0;
            float* kd = ks + r*KPAD + c0;
            float* vd = vs + r*VPAD + c0;
            #pragma unroll
            for (int i = 0; i < 4; i++) {
                float4 kv = *(const float4*)(ksrc + i*4);
                float4 vv = *(const float4*)(vsrc + i*4);
                kd[i*4+0]=tf32f(kv.x); kd[i*4+1]=tf32f(kv.y);
                kd[i*4+2]=tf32f(kv.z); kd[i*4+3]=tf32f(kv.w);
                vd[i*4+0]=tf32f(vv.x); vd[i*4+1]=tf32f(vv.y);
                vd[i*4+2]=tf32f(vv.z); vd[i*4+3]=tf32f(vv.w);
            }
        }
        __syncthreads();

        // ---- S = Q @ K^T : warp covers 16 rows x all 64 keys ----
        float s[8][4] = {};
        #pragma unroll
        for (int nt = 0; nt < 8; nt++) {
            const float* bb = ks + (nt*8 + g)*KPAD;
            #pragma unroll
            for (int kc = 0; kc < 8; kc++) {
                unsigned b0 = __float_as_uint(bb[kc*8 + t]);
                unsigned b1 = __float_as_uint(bb[kc*8 + t + 4]);
                mma_tf32(s[nt], qf[kc], b0, b1);
            }
        }

        // ---- register online softmax (rows r0=w*16+g, r1=r0+8) ----
        float mx0 = -1e30f, mx1 = -1e30f;
        #pragma unroll
        for (int nt = 0; nt < 8; nt++) {
            mx0 = fmaxf(mx0, fmaxf(s[nt][0], s[nt][1]));
            mx1 = fmaxf(mx1, fmaxf(s[nt][2], s[nt][3]));
        }
        mx0 = fmaxf(mx0, __shfl_xor_sync(0xffffffffu, mx0, 1));
        mx0 = fmaxf(mx0, __shfl_xor_sync(0xffffffffu, mx0, 2));
        mx1 = fmaxf(mx1, __shfl_xor_sync(0xffffffffu, mx1, 1));
        mx1 = fmaxf(mx1, __shfl_xor_sync(0xffffffffu, mx1, 2));
        float mn0 = fmaxf(m0, mx0), mn1 = fmaxf(m1, mx1);
        float f0 = __expf(m0 - mn0), f1 = __expf(m1 - mn1);
        float sum0 = 0.f, sum1 = 0.f;
        #pragma unroll
        for (int nt = 0; nt < 8; nt++) {
            float e0 = __expf(s[nt][0] - mn0);
            float e1 = __expf(s[nt][1] - mn0);
            float e2 = __expf(s[nt][2] - mn1);
            float e3 = __expf(s[nt][3] - mn1);
            sum0 += e0 + e1; sum1 += e2 + e3;
            s[nt][0] = tf32f(e0); s[nt][1] = tf32f(e1);
            s[nt][2] = tf32f(e2); s[nt][3] = tf32f(e3);
        }
        sum0 += __shfl_xor_sync(0xffffffffu, sum0, 1);
        sum0 += __shfl_xor_sync(0xffffffffu, sum0, 2);
        sum1 += __shfl_xor_sync(0xffffffffu, sum1, 1);
        sum1 += __shfl_xor_sync(0xffffffffu, sum1, 2);
        l0 = l0*f0 + sum0; l1 = l1*f1 + sum1;
        m0 = mn0; m1 = mn1;
        #pragma unroll
        for (int nt = 0; nt < 8; nt++) {
            of[nt][0] *= f0; of[nt][1] *= f0;
            of[nt][2] *= f1; of[nt][3] *= f1;
        }

        // ---- O += P @ V : P C-frag -> A-frag via in-warp shuffles ----
        int src0 = (lane & ~3) | (t >> 1);   // holder of col t   (within g-group)
        int src1 = src0 + 2;                 // holder of col t+4
        bool odd = (t & 1);
        #pragma unroll
        for (int kc = 0; kc < 8; kc++) {
            float v00 = __shfl_sync(0xffffffffu, s[kc][0], src0);
            float v01 = __shfl_sync(0xffffffffu, s[kc][1], src0);
            float v10 = __shfl_sync(0xffffffffu, s[kc][2], src0);
            float v11 = __shfl_sync(0xffffffffu, s[kc][3], src0);
            float w00 = __shfl_sync(0xffffffffu, s[kc][0], src1);
            float w01 = __shfl_sync(0xffffffffu, s[kc][1], src1);
            float w10 = __shfl_sync(0xffffffffu, s[kc][2], src1);
            float w11 = __shfl_sync(0xffffffffu, s[kc][3], src1);
            unsigned a[4];
            a[0] = __float_as_uint(odd ? v01 : v00);   // P[r0][kc*8+t]
            a[1] = __float_as_uint(odd ? v11 : v10);   // P[r1][kc*8+t]
            a[2] = __float_as_uint(odd ? w01 : w00);   // P[r0][kc*8+t+4]
            a[3] = __float_as_uint(odd ? w11 : w10);   // P[r1][kc*8+t+4]
            const float* vb0 = vs + (kc*8 + t)*VPAD + g;
            const float* vb1 = vs + (kc*8 + t + 4)*VPAD + g;
            #pragma unroll
            for (int nt = 0; nt < 8; nt++) {
                unsigned b0 = __float_as_uint(vb0[nt*8]);
                unsigned b1 = __float_as_uint(vb1[nt*8]);
                mma_tf32(of[nt], a, b0, b1);
            }
        }
        __syncthreads();
    }

    // ---- epilogue ----
    float il0 = 1.f / l0, il1 = 1.f / l1;
    int r0 = wid*16 + g;
    #pragma unroll
    for (int nt = 0; nt < 8; nt++) {
        int c = nt*8 + 2*t;
        float* o0 = O + ((size_t)bh*NS + q0 + r0)*ND + c;
        float* o1 = o0 + 8*ND;
        *(float2*)o0 = make_float2(of[nt][0]*il0, of[nt][1]*il0);
        *(float2*)o1 = make_float2(of[nt][2]*il1, of[nt][3]*il1);
    }
}

// ============ out projection + residual (merged both directions) ============
__global__ void outproj_tf32_kernel(const float* __restrict__ w_i2t, const float* __restrict__ b_i2t,
                                    const float* __restrict__ w_t2i, const float* __restrict__ b_t2i) {
    __shared__ __align__(16) float Xs[64*QPA];
    __shared__ __align__(16) float Wsm[64*QPA];
    int which = blockIdx.z;
    const float* out_w = which ? w_t2i : w_i2t;
    const float* out_b = which ? b_t2i : b_i2t;
    int bh = blockIdx.y, h = bh & (NH-1), s0 = blockIdx.x*64;
    int tid = threadIdx.x;
    int wid = tid >> 5, lane = tid & 31;
    int wm = wid >> 1, wn = wid & 1;
    int g = lane >> 2, t = lane & 3;
    int fr0 = wm*16 + g;
    int lr = tid >> 4, lc = (tid & 15) * 4;
    const float* xbase = g_o[which] + ((size_t)bh*NS + s0)*ND;
    const float* wsrc  = out_w + (size_t)h*64*64;
    #pragma unroll
    for (int i = 0; i < 4; i++) {
        int r = lr + i*16;
        float4 x = *(const float4*)(xbase + r*ND + lc);
        float4 w = *(const float4*)(wsrc  + r*64 + lc);
        float* xd = Xs + r*QPA + lc;
        float* wd = Wsm + r*QPA + lc;
        xd[0]=tf32f(x.x); xd[1]=tf32f(x.y); xd[2]=tf32f(x.z); xd[3]=tf32f(x.w);
        wd[0]=tf32f(w.x); wd[1]=tf32f(w.y); wd[2]=tf32f(w.z); wd[3]=tf32f(w.w);
    }
    __syncthreads();
    float acc[4][4] = {};
    #pragma unroll
    for (int kc = 0; kc < 8; kc++) {
        const float* ab = Xs + fr0*QPA + kc*8 + t;
        unsigned a[4];
        a[0]=__float_as_uint(ab[0]);  a[1]=__float_as_uint(ab[8*QPA]);
        a[2]=__float_as_uint(ab[4]);  a[3]=__float_as_uint(ab[8*QPA+4]);
        #pragma unroll
        for (int nt = 0; nt < 4; nt++) {
            const float* bb = Wsm + (wn*32 + nt*8 + g)*QPA + kc*8 + t;
            mma_tf32(acc[nt], a, __float_as_uint(bb[0]), __float_as_uint(bb[4]));
        }
    }
    const float* resid = g_c[which];
    int off = which * 64;
    #pragma unroll
    for (int nt = 0; nt < 4; nt++) {
        int c = wn*32 + nt*8 + 2*t;
        float bx = out_b[h*64+c], by = out_b[h*64+c+1];
        int s0r = s0 + fr0, s1r = s0 + fr0 + 8;
        const float* r0 = resid + ((size_t)bh*NS + s0r)*ND + c;
        const float* r1 = resid + ((size_t)bh*NS + s1r)*ND + c;
        float* d0 = g_comb + ((size_t)bh*NS + s0r)*128 + off + c;
        float* d1 = g_comb + ((size_t)bh*NS + s1r)*128 + off + c;
        *(float2*)d0 = make_float2(acc[nt][0]+bx+r0[0], acc[nt][1]+by+r0[1]);
        *(float2*)d1 = make_float2(acc[nt][2]+bx+r1[0], acc[nt][3]+by+r1[1]);
    }
}

// ---------------- final LN over concat dim (128) ----------------
__global__ void final_ln_kernel(const float* __restrict__ hg, const float* __restrict__ hb,
                                float* __restrict__ out) {
    int row = blockIdx.x * 8 + (threadIdx.x >> 5);
    int lane = threadIdx.x & 31;
    const float* x = g_comb + (size_t)row * 128;
    float v[4], sum = 0.f;
    #pragma unroll
    for (int i=0;i<4;i++){ v[i] = x[lane + i*32]; sum += v[i]; }
    #pragma unroll
    for (int o = 16; o > 0; o >>= 1) sum += __shfl_xor_sync(0xffffffffu, sum, o);
    float mu = sum * (1.f/128.f);
    float sq = 0.f;
    #pragma unroll
    for (int i=0;i<4;i++){ float d = v[i]-mu; sq += d*d; }
    #pragma unroll
    for (int o = 16; o > 0; o >>= 1) sq += __shfl_xor_sync(0xffffffffu, sq, o);
    float rstd = rsqrtf(sq*(1.f/128.f) + 1e-5f);
    int h = (row >> 9) & 15;
    #pragma unroll
    for (int i=0;i<4;i++){
        int c = lane + i*32;
        out[(size_t)row*128 + c] = (v[i]-mu)*rstd*hg[h*128+c] + hb[h*128+c];
    }
}

// ---------------- launch ----------------
extern "C" void kernel_launch(void* const* d_in, const int* in_sizes, int n_in,
                              void* d_out, int out_size) {
    const float* image     = (const float*)d_in[0];
    const float* text      = (const float*)d_in[1];
    const float* img_w     = (const float*)d_in[2];
    const float* img_b     = (const float*)d_in[3];
    const float* img_g     = (const float*)d_in[4];
    const float* img_lb    = (const float*)d_in[5];
    const float* txt_w     = (const float*)d_in[6];
    const float* txt_b     = (const float*)d_in[7];
    const float* txt_g     = (const float*)d_in[8];
    const float* txt_lb    = (const float*)d_in[9];
    const float* i2t_in_w  = (const float*)d_in[10];
    const float* i2t_in_b  = (const float*)d_in[11];
    const float* i2t_out_w = (const float*)d_in[12];
    const float* i2t_out_b = (const float*)d_in[13];
    const float* t2i_in_w  = (const float*)d_in[14];
    const float* t2i_in_b  = (const float*)d_in[15];
    const float* t2i_out_w = (const float*)d_in[16];
    const float* t2i_out_b = (const float*)d_in[17];
    const float* hn_g      = (const float*)d_in[18];
    const float* hn_b      = (const float*)d_in[19];
    float* out = (float*)d_out;

    const int QKV_SMEM = 3*64*QPA*4;   // 52224 B
    static int attrs_set = 0;
    if (!attrs_set) {
        cudaFuncSetAttribute(qkv_tf32_kernel, cudaFuncAttributeMaxDynamicSharedMemorySize, QKV_SMEM);
        attrs_set = 1;
    }

    dim3 thr(256);
    gemm_tf32_kernel<<<dim3(8,64), thr>>>(image, img_w, img_b, 768, 0);
    gemm_tf32_kernel<<<dim3(8,64), thr>>>(text,  txt_w, txt_b, 512, 1);
    ln_l2_kernel<<<dim3(8192,2), thr>>>(img_g, img_lb, txt_g, txt_lb);
    qkv_tf32_kernel<<<dim3(8,256,2), thr, QKV_SMEM>>>(i2t_in_w, i2t_in_b, t2i_in_w, t2i_in_b);
    attn_kernel<<<dim3(4,256,2), thr>>>();
    outproj_tf32_kernel<<<dim3(8,256,2), thr>>>(i2t_out_w, i2t_out_b, t2i_out_w, t2i_out_b);
    final_ln_kernel<<<16384, thr>>>(hn_g, hn_b, out);
}